// round 5
// baseline (speedup 1.0000x reference)
#include <cuda_runtime.h>
#include <cstdint>
#include <math.h>

#define DET 512
#define NTH 180
#define B   4
#define OUT 362
#define RAD 181          // OUT//2 per reference
#define PI_F 3.14159265358979323846f

#define DSLOT 516        // 512 dets + 4 zero-pad det slots
#define OOB   513        // pad det: slots 512..515 are zero
#define STG   3          // cp.async ring stages

// filtered projections, INTERLEAVED layout [a][det][b] (b fastest, 16B units)
__device__ float g_filt[NTH * DET * B];

// ---------------------------------------------------------------------------
// Kernel 1: ramp filter as direct symmetric convolution (exact equivalent of
// the reference FFT ramp filter with 512-zero circular pad).
//   out[k] = 0.5*x[k] + sum_{d odd} g(d) * (x[k-d] + x[k+d]),  g(d)=-2/(pi d)^2
// Zero-padded signal in smem makes the inner loop branch-free with
// immediate-offset LDS. Writes interleaved g_filt[a][k][b].
// ---------------------------------------------------------------------------
__global__ void __launch_bounds__(DET) filter_kernel(const float* __restrict__ x)
{
    __shared__ float xsp[3 * DET];   // [0,512)=0, [512,1024)=signal, [1024,1536)=0
    __shared__ float gt_o[DET / 2];  // g(2u+1)

    const int a = blockIdx.x;
    const int b = blockIdx.y;
    const int k = threadIdx.x;

    // x layout: (B,1,DET,NTH) -> x[b, m, a] = x[(b*DET + m)*NTH + a]
    xsp[k]            = 0.0f;
    xsp[2 * DET + k]  = 0.0f;
    xsp[DET + k]      = x[(b * DET + k) * NTH + a];
    if (k < DET / 2) {
        float fd = (float)(2 * k + 1);
        gt_o[k] = -2.0f / (PI_F * PI_F * fd * fd);
    }
    __syncthreads();

    const float* xc = xsp + DET + k;   // centered pointer
    float s = 0.5f * xc[0];
    #pragma unroll 8
    for (int u = 0; u < DET / 2; u++) {
        int d = 2 * u + 1;
        s = fmaf(gt_o[u], xc[-d] + xc[d], s);
    }
    g_filt[(a * DET + k) * B + b] = s;
}

// ---------------------------------------------------------------------------
// Kernel 2: backprojection. 32x32 pixel tile, all 4 batches per block,
// 512 threads (2 pixel-rows x 4 batches per thread). Batch-interleaved
// detector rows in smem -> 2x LDS.128 per (row,angle). 3-stage cp.async
// ring, one __syncthreads per angle.
// pos = (j-RAD)*cos(th) - (i-RAD)*sin(th) + DET/2
// ---------------------------------------------------------------------------
__global__ void __launch_bounds__(512) backproj_kernel(float* __restrict__ out)
{
    __shared__ __align__(16) float rowsI[STG][DSLOT * B]; // 3*8256B = 24768B
    __shared__ float cs[NTH];
    __shared__ float sn[NTH];

    const int j0 = blockIdx.x * 32;
    const int i0 = blockIdx.y * 32;
    const int tid = threadIdx.x;
    const int tx = tid & 31;             // column j within tile
    const int ty = tid >> 5;             // 0..15, pixel-row group

    if (tid < NTH) {
        float ang = (float)tid * (PI_F / 180.0f);
        cs[tid] = cosf(ang);
        sn[tid] = sinf(ang);
    }
    // zero pad det slots 512..515 for every stage: 3*4*4 = 48 floats
    if (tid < STG * 16) {
        int p  = tid & 15;
        int st = tid >> 4;
        rowsI[st][DET * B + p] = 0.0f;
    }

    // staging: thread tid copies the 16B interleaved chunk of det=tid
    const float* gsrc = g_filt + tid * B;        // + a*DET*B per angle
    unsigned int sdst[STG];
    #pragma unroll
    for (int st = 0; st < STG; st++) {
        unsigned int u;
        asm("{ .reg .u64 t; cvta.to.shared.u64 t, %1; cvt.u32.u64 %0, t; }"
            : "=r"(u) : "l"((const void*)&rowsI[st][tid * B]));
        sdst[st] = u;
    }

    // prologue: prefetch angles 0 and 1 into stages 0 and 1
    #pragma unroll
    for (int a = 0; a < 2; a++) {
        asm volatile("cp.async.ca.shared.global [%0], [%1], 16;\n"
                     :: "r"(sdst[a]), "l"(gsrc + a * DET * B) : "memory");
        asm volatile("cp.async.commit_group;\n" ::: "memory");
    }

    const float jf = (float)(j0 + tx - RAD);
    float xpr[2];
    xpr[0] = (float)(i0 + ty - RAD);
    xpr[1] = (float)(i0 + ty + 16 - RAD);

    float acc[2][B];
    #pragma unroll
    for (int r = 0; r < 2; r++)
        #pragma unroll
        for (int bb = 0; bb < B; bb++) acc[r][bb] = 0.0f;

    int st = 0;
    for (int a = 0; a < NTH; a++) {
        if (a < NTH - 2) {
            asm volatile("cp.async.wait_group 1;\n" ::: "memory");
        } else {
            asm volatile("cp.async.wait_group 0;\n" ::: "memory");
        }
        __syncthreads();   // angle a staged & visible; stage (st+2)%3 is free

        if (a + 2 < NTH) {
            int nst = st + 2; if (nst >= STG) nst -= STG;
            asm volatile("cp.async.ca.shared.global [%0], [%1], 16;\n"
                         :: "r"(sdst[nst]), "l"(gsrc + (a + 2) * DET * B)
                         : "memory");
            asm volatile("cp.async.commit_group;\n" ::: "memory");
        }

        const float c = cs[a];
        const float s = sn[a];
        const float base = fmaf(jf, c, (float)(DET / 2));
        const float* rw = rowsI[st];

        #pragma unroll
        for (int r = 0; r < 2; r++) {
            float pos = fmaf(-xpr[r], s, base);
            int   idx = __float2int_rd(pos);
            float w   = pos - (float)idx;
            // exact reference gate: contributes 0 unless 0 <= pos <= det-1
            int sel = (pos >= 0.0f && pos <= (float)(DET - 1)) ? idx : OOB;
            const float4 q0 = *reinterpret_cast<const float4*>(rw + sel * B);
            const float4 q1 = *reinterpret_cast<const float4*>(rw + sel * B + B);
            float omw = 1.0f - w;
            acc[r][0] = fmaf(omw, q0.x, acc[r][0]);
            acc[r][0] = fmaf(w,   q1.x, acc[r][0]);
            acc[r][1] = fmaf(omw, q0.y, acc[r][1]);
            acc[r][1] = fmaf(w,   q1.y, acc[r][1]);
            acc[r][2] = fmaf(omw, q0.z, acc[r][2]);
            acc[r][2] = fmaf(w,   q1.z, acc[r][2]);
            acc[r][3] = fmaf(omw, q0.w, acc[r][3]);
            acc[r][3] = fmaf(w,   q1.w, acc[r][3]);
        }

        st++; if (st >= STG) st -= STG;
    }

    const float scale = PI_F / (2.0f * (float)NTH);
    const int j = j0 + tx;
    if (j < OUT) {
        #pragma unroll
        for (int r = 0; r < 2; r++) {
            int i = i0 + ty + 16 * r;
            if (i < OUT) {
                #pragma unroll
                for (int bb = 0; bb < B; bb++)
                    out[(bb * OUT + i) * OUT + j] = acc[r][bb] * scale;
            }
        }
    }
}

extern "C" void kernel_launch(void* const* d_in, const int* in_sizes, int n_in,
                              void* d_out, int out_size)
{
    const float* x = (const float*)d_in[0];
    float* out = (float*)d_out;

    filter_kernel<<<dim3(NTH, B), DET>>>(x);

    dim3 grid((OUT + 31) / 32, (OUT + 31) / 32);   // 12 x 12, one wave
    backproj_kernel<<<grid, 512>>>(out);
}

// round 6
// speedup vs baseline: 2.3476x; 2.3476x over previous
#include <cuda_runtime.h>
#include <cstdint>
#include <math.h>

#define DET 512
#define NTH 180
#define B   4
#define OUT 362
#define RAD 181          // OUT//2 per reference
#define PI_F 3.14159265358979323846f

#define ROWLEN 516       // 512 data + 4 zero-pad slots
#define OOB    513       // pad slot: row[513]=row[514]=0
#define STG    3         // cp.async ring stages
#define NSPLIT 4         // angle splits
#define APB    45        // angles per block (180/4)

// filtered projections, layout [b][a][det]
__device__ float g_filt[B * NTH * DET];
// partial backprojections, layout [z][b][i][j]
__device__ float g_part[NSPLIT * B * OUT * OUT];

// ---------------------------------------------------------------------------
// Kernel 1: ramp filter as two dense parity-compressed correlations.
//   out[k] = 0.5 x[k] + sum_{d odd} g(d) x[k-d],  g(d) = -2/(pi d)^2
// even k=2K:  out_e[K] = 0.5 xe[K] + sum_M T[K-M+256] xo[M]
// odd  k=2K+1: out_o[K] = 0.5 xo[K] + sum_M T[M-K+256] xe[M]
// where T[j] = g(|2j-513|).  128 threads, 4 outputs each, register-tiled.
// ---------------------------------------------------------------------------
__global__ void __launch_bounds__(128) filter_kernel(const float* __restrict__ x)
{
    __shared__ __align__(16) float xe[256];
    __shared__ __align__(16) float xo[256];
    __shared__ __align__(16) float T[512];

    const int a = blockIdx.x;
    const int b = blockIdx.y;
    const int tid = threadIdx.x;

    // load x: m = 4*tid .. 4*tid+3 ; x[b, m, a] = x[(b*DET+m)*NTH + a]
    {
        int m0 = 4 * tid;
        const float* xp = x + (b * DET + m0) * NTH + a;
        float v0 = xp[0 * NTH], v1 = xp[1 * NTH];
        float v2 = xp[2 * NTH], v3 = xp[3 * NTH];
        xe[m0 / 2]     = v0;  xo[m0 / 2]     = v1;
        xe[m0 / 2 + 1] = v2;  xo[m0 / 2 + 1] = v3;
    }
    // T table
    #pragma unroll
    for (int j = tid; j < 512; j += 128) {
        int d = 2 * j - 513; if (d < 0) d = -d;
        float fd = (float)d;
        T[j] = -2.0f / (PI_F * PI_F * fd * fd);
    }
    __syncthreads();

    const int odd = tid >> 6;            // warps 0-1 even outputs, 2-3 odd
    const int t   = tid & 63;
    const int K0  = 4 * t;
    const float* xopp  = odd ? xe : xo;
    const float* xsame = odd ? xo : xe;

    float acc0 = 0.f, acc1 = 0.f, acc2 = 0.f, acc3 = 0.f;
    #pragma unroll 4
    for (int M0 = 0; M0 < 256; M0 += 4) {
        float4 xb = *reinterpret_cast<const float4*>(xopp + M0);   // broadcast
        int j0 = odd ? (M0 - K0 + 256) : (K0 - M0 + 256);          // in [4,508]
        float4 ta = *reinterpret_cast<const float4*>(T + j0 - 4);  // T[j0-4..j0-1]
        float4 tb = *reinterpret_cast<const float4*>(T + j0);      // T[j0..j0+3]
        if (!odd) {
            // acc[i] += T[j0 + i - mt] * xb[mt]
            acc0 = fmaf(tb.x, xb.x, acc0); acc0 = fmaf(ta.w, xb.y, acc0);
            acc0 = fmaf(ta.z, xb.z, acc0); acc0 = fmaf(ta.y, xb.w, acc0);
            acc1 = fmaf(tb.y, xb.x, acc1); acc1 = fmaf(tb.x, xb.y, acc1);
            acc1 = fmaf(ta.w, xb.z, acc1); acc1 = fmaf(ta.z, xb.w, acc1);
            acc2 = fmaf(tb.z, xb.x, acc2); acc2 = fmaf(tb.y, xb.y, acc2);
            acc2 = fmaf(tb.x, xb.z, acc2); acc2 = fmaf(ta.w, xb.w, acc2);
            acc3 = fmaf(tb.w, xb.x, acc3); acc3 = fmaf(tb.z, xb.y, acc3);
            acc3 = fmaf(tb.y, xb.z, acc3); acc3 = fmaf(tb.x, xb.w, acc3);
        } else {
            // acc[i] += T[j0 + mt - i] * xb[mt]
            acc0 = fmaf(tb.x, xb.x, acc0); acc0 = fmaf(tb.y, xb.y, acc0);
            acc0 = fmaf(tb.z, xb.z, acc0); acc0 = fmaf(tb.w, xb.w, acc0);
            acc1 = fmaf(ta.w, xb.x, acc1); acc1 = fmaf(tb.x, xb.y, acc1);
            acc1 = fmaf(tb.y, xb.z, acc1); acc1 = fmaf(tb.z, xb.w, acc1);
            acc2 = fmaf(ta.z, xb.x, acc2); acc2 = fmaf(ta.w, xb.y, acc2);
            acc2 = fmaf(tb.x, xb.z, acc2); acc2 = fmaf(tb.y, xb.w, acc2);
            acc3 = fmaf(ta.y, xb.x, acc3); acc3 = fmaf(ta.z, xb.y, acc3);
            acc3 = fmaf(ta.w, xb.z, acc3); acc3 = fmaf(tb.x, xb.w, acc3);
        }
    }
    float4 xc = *reinterpret_cast<const float4*>(xsame + K0);
    acc0 = fmaf(0.5f, xc.x, acc0);
    acc1 = fmaf(0.5f, xc.y, acc1);
    acc2 = fmaf(0.5f, xc.z, acc2);
    acc3 = fmaf(0.5f, xc.w, acc3);

    // dets: even thread -> 8t,8t+2,8t+4,8t+6 ; odd -> 8t+1,...
    float* o = g_filt + (b * NTH + a) * DET + 8 * t + odd;
    o[0] = acc0; o[2] = acc1; o[4] = acc2; o[6] = acc3;
}

// ---------------------------------------------------------------------------
// Kernel 2: backprojection, angle-split 4 ways. 32x32 tile, 256 threads,
// 4 pixel-rows x 4 batches per thread, scalar LDS, 3-stage cp.async ring,
// one __syncthreads per angle. Writes partial sums to g_part[z].
// pos = (j-RAD)*cos(th) - (i-RAD)*sin(th) + DET/2
// ---------------------------------------------------------------------------
__global__ void __launch_bounds__(256) backproj_kernel()
{
    __shared__ float rows[STG][B][ROWLEN];   // 24768 B
    __shared__ float cs[APB];
    __shared__ float sn[APB];

    const int z  = blockIdx.z;
    const int a0 = z * APB;
    const int j0 = blockIdx.x * 32;
    const int i0 = blockIdx.y * 32;
    const int tid = threadIdx.x;
    const int tx = tid & 31;
    const int ty = tid >> 5;             // 0..7

    if (tid < APB) {
        float ang = (float)(a0 + tid) * (PI_F / 180.0f);
        cs[tid] = cosf(ang);
        sn[tid] = sinf(ang);
    }
    // zero pad slots: STG*B*4 = 48 floats
    if (tid < STG * 16) {
        int p  = tid & 3;
        int bb = (tid >> 2) & 3;
        int st = tid >> 4;
        rows[st][bb][512 + p] = 0.0f;
    }

    // staging: thread copies 16B chunk c16 of batch rows rA and rA+2
    const int rA  = tid >> 7;            // 0 or 1
    const int c16 = tid & 127;
    const float* gA = g_filt + ((rA)     * NTH + a0) * DET + c16 * 4;
    const float* gB = g_filt + ((rA + 2) * NTH + a0) * DET + c16 * 4;
    unsigned int dA[STG], dB[STG];
    #pragma unroll
    for (int st = 0; st < STG; st++) {
        unsigned int u;
        asm("{ .reg .u64 t; cvta.to.shared.u64 t, %1; cvt.u32.u64 %0, t; }"
            : "=r"(u) : "l"((const void*)&rows[st][rA][c16 * 4]));
        dA[st] = u;
        asm("{ .reg .u64 t; cvta.to.shared.u64 t, %1; cvt.u32.u64 %0, t; }"
            : "=r"(u) : "l"((const void*)&rows[st][rA + 2][c16 * 4]));
        dB[st] = u;
    }

    // prologue: prefetch local angles 0 and 1 into stages 0 and 1
    #pragma unroll
    for (int q = 0; q < 2; q++) {
        asm volatile("cp.async.ca.shared.global [%0], [%1], 16;\n"
                     :: "r"(dA[q]), "l"(gA + q * DET) : "memory");
        asm volatile("cp.async.ca.shared.global [%0], [%1], 16;\n"
                     :: "r"(dB[q]), "l"(gB + q * DET) : "memory");
        asm volatile("cp.async.commit_group;\n" ::: "memory");
    }

    const float jf = (float)(j0 + tx - RAD);
    float xpr[4];
    #pragma unroll
    for (int r = 0; r < 4; r++) xpr[r] = (float)(i0 + ty + 8 * r - RAD);

    float acc[B][4];
    #pragma unroll
    for (int bb = 0; bb < B; bb++)
        #pragma unroll
        for (int r = 0; r < 4; r++) acc[bb][r] = 0.0f;

    int st = 0;
    for (int q = 0; q < APB; q++) {
        if (q < APB - 2) {
            asm volatile("cp.async.wait_group 1;\n" ::: "memory");
        } else {
            asm volatile("cp.async.wait_group 0;\n" ::: "memory");
        }
        __syncthreads();   // angle q staged & visible; stage (st+2)%3 free

        if (q + 2 < APB) {
            int nst = st + 2; if (nst >= STG) nst -= STG;
            asm volatile("cp.async.ca.shared.global [%0], [%1], 16;\n"
                         :: "r"(dA[nst]), "l"(gA + (q + 2) * DET) : "memory");
            asm volatile("cp.async.ca.shared.global [%0], [%1], 16;\n"
                         :: "r"(dB[nst]), "l"(gB + (q + 2) * DET) : "memory");
            asm volatile("cp.async.commit_group;\n" ::: "memory");
        }

        const float c = cs[q];
        const float s = sn[q];
        const float base = fmaf(jf, c, (float)(DET / 2));
        const float* r0 = rows[st][0];
        const float* r1 = rows[st][1];
        const float* r2 = rows[st][2];
        const float* r3 = rows[st][3];

        #pragma unroll
        for (int r = 0; r < 4; r++) {
            float pos = fmaf(-xpr[r], s, base);
            int   idx = __float2int_rd(pos);
            float w   = pos - (float)idx;
            float omw = 1.0f - w;
            // exact reference gate: contributes 0 unless 0 <= pos <= det-1
            int sel = (pos >= 0.0f && pos <= (float)(DET - 1)) ? idx : OOB;
            acc[0][r] = fmaf(omw, r0[sel], acc[0][r]);
            acc[0][r] = fmaf(w,   r0[sel + 1], acc[0][r]);
            acc[1][r] = fmaf(omw, r1[sel], acc[1][r]);
            acc[1][r] = fmaf(w,   r1[sel + 1], acc[1][r]);
            acc[2][r] = fmaf(omw, r2[sel], acc[2][r]);
            acc[2][r] = fmaf(w,   r2[sel + 1], acc[2][r]);
            acc[3][r] = fmaf(omw, r3[sel], acc[3][r]);
            acc[3][r] = fmaf(w,   r3[sel + 1], acc[3][r]);
        }

        st++; if (st >= STG) st -= STG;
    }

    const int j = j0 + tx;
    if (j < OUT) {
        float* pz = g_part + z * (B * OUT * OUT);
        #pragma unroll
        for (int bb = 0; bb < B; bb++) {
            #pragma unroll
            for (int r = 0; r < 4; r++) {
                int i = i0 + ty + 8 * r;
                if (i < OUT)
                    pz[(bb * OUT + i) * OUT + j] = acc[bb][r];
            }
        }
    }
}

// ---------------------------------------------------------------------------
// Kernel 3: combine the NSPLIT partial sums and scale.
// ---------------------------------------------------------------------------
__global__ void __launch_bounds__(256) combine_kernel(float* __restrict__ out)
{
    const int n = B * OUT * OUT;
    int idx = blockIdx.x * 256 + threadIdx.x;
    if (idx < n) {
        float v = g_part[idx] + g_part[n + idx]
                + g_part[2 * n + idx] + g_part[3 * n + idx];
        out[idx] = v * (PI_F / (2.0f * (float)NTH));
    }
}

extern "C" void kernel_launch(void* const* d_in, const int* in_sizes, int n_in,
                              void* d_out, int out_size)
{
    const float* x = (const float*)d_in[0];
    float* out = (float*)d_out;

    filter_kernel<<<dim3(NTH, B), 128>>>(x);

    dim3 grid((OUT + 31) / 32, (OUT + 31) / 32, NSPLIT);   // 12 x 12 x 4
    backproj_kernel<<<grid, 256>>>();

    int n = B * OUT * OUT;
    combine_kernel<<<(n + 255) / 256, 256>>>(out);
}

// round 7
// speedup vs baseline: 2.5216x; 1.0741x over previous
#include <cuda_runtime.h>
#include <cstdint>
#include <math.h>

#define DET 512
#define NTH 180
#define B   4
#define OUT 362
#define RAD 181          // OUT//2 per reference
#define PI_F 3.14159265358979323846f

#define ROWLEN 516       // 512 data + 4 zero-pad slots
#define OOB    513       // pad slot: row[513]=row[514]=0
#define STG    3         // cp.async ring stages
#define NSPLIT 6         // angle splits -> 12*12*6 = 864 blocks (one wave)
#define APB    30        // angles per block (180/6)

// filtered projections, layout [b][a][det]
__device__ float g_filt[B * NTH * DET];
// partial backprojections, layout [z][b][i][j]
__device__ float g_part[NSPLIT * B * OUT * OUT];

// ---------------------------------------------------------------------------
// Kernel 1: ramp filter as two dense parity-compressed correlations.
//   out[k] = 0.5 x[k] + sum_{d odd} g(d) x[k-d],  g(d) = -2/(pi d)^2
// even k=2K:  out_e[K] = 0.5 xe[K] + sum_M T[K-M+256] xo[M]
// odd  k=2K+1: out_o[K] = 0.5 xo[K] + sum_M T[M-K+256] xe[M]
// T[j] = g(|2j-513|). 128 threads, 4 outputs each; T window register-shifted
// so only ONE float4 of T is loaded per 4-tap group.
// ---------------------------------------------------------------------------
__global__ void __launch_bounds__(128) filter_kernel(const float* __restrict__ x)
{
    __shared__ __align__(16) float xe[256];
    __shared__ __align__(16) float xo[256];
    __shared__ __align__(16) float T[512];

    const int a = blockIdx.x;
    const int b = blockIdx.y;
    const int tid = threadIdx.x;

    // load x: m = 4*tid .. 4*tid+3 ; x[b, m, a] = x[(b*DET+m)*NTH + a]
    {
        int m0 = 4 * tid;
        const float* xp = x + (b * DET + m0) * NTH + a;
        float v0 = xp[0 * NTH], v1 = xp[1 * NTH];
        float v2 = xp[2 * NTH], v3 = xp[3 * NTH];
        xe[m0 / 2]     = v0;  xo[m0 / 2]     = v1;
        xe[m0 / 2 + 1] = v2;  xo[m0 / 2 + 1] = v3;
    }
    #pragma unroll
    for (int j = tid; j < 512; j += 128) {
        int d = 2 * j - 513; if (d < 0) d = -d;
        float fd = (float)d;
        T[j] = -2.0f / (PI_F * PI_F * fd * fd);
    }
    __syncthreads();

    const int odd = tid >> 6;            // warps 0-1 even outputs, 2-3 odd
    const int t   = tid & 63;
    const int K0  = 4 * t;

    float acc0 = 0.f, acc1 = 0.f, acc2 = 0.f, acc3 = 0.f;

    if (!odd) {
        // j0 = K0 - M0 + 256 decreases by 4 each step; next tb == current ta
        int j0 = K0 + 256;
        float4 tb = *reinterpret_cast<const float4*>(T + j0);
        #pragma unroll 4
        for (int M0 = 0; M0 < 256; M0 += 4, j0 -= 4) {
            float4 xb = *reinterpret_cast<const float4*>(xo + M0);   // broadcast
            float4 ta = *reinterpret_cast<const float4*>(T + j0 - 4);
            // acc[i] += T[j0 + i - mt] * xb[mt]
            acc0 = fmaf(tb.x, xb.x, acc0); acc0 = fmaf(ta.w, xb.y, acc0);
            acc0 = fmaf(ta.z, xb.z, acc0); acc0 = fmaf(ta.y, xb.w, acc0);
            acc1 = fmaf(tb.y, xb.x, acc1); acc1 = fmaf(tb.x, xb.y, acc1);
            acc1 = fmaf(ta.w, xb.z, acc1); acc1 = fmaf(ta.z, xb.w, acc1);
            acc2 = fmaf(tb.z, xb.x, acc2); acc2 = fmaf(tb.y, xb.y, acc2);
            acc2 = fmaf(tb.x, xb.z, acc2); acc2 = fmaf(ta.w, xb.w, acc2);
            acc3 = fmaf(tb.w, xb.x, acc3); acc3 = fmaf(tb.z, xb.y, acc3);
            acc3 = fmaf(tb.y, xb.z, acc3); acc3 = fmaf(tb.x, xb.w, acc3);
            tb = ta;
        }
        float4 xc = *reinterpret_cast<const float4*>(xe + K0);
        acc0 = fmaf(0.5f, xc.x, acc0);
        acc1 = fmaf(0.5f, xc.y, acc1);
        acc2 = fmaf(0.5f, xc.z, acc2);
        acc3 = fmaf(0.5f, xc.w, acc3);
    } else {
        // j0 = M0 - K0 + 256 increases by 4; next ta == current tb
        int j0 = 256 - K0;
        float4 ta = *reinterpret_cast<const float4*>(T + j0 - 4);
        #pragma unroll 4
        for (int M0 = 0; M0 < 256; M0 += 4, j0 += 4) {
            float4 xb = *reinterpret_cast<const float4*>(xe + M0);   // broadcast
            float4 tb = *reinterpret_cast<const float4*>(T + j0);
            // acc[i] += T[j0 + mt - i] * xb[mt]
            acc0 = fmaf(tb.x, xb.x, acc0); acc0 = fmaf(tb.y, xb.y, acc0);
            acc0 = fmaf(tb.z, xb.z, acc0); acc0 = fmaf(tb.w, xb.w, acc0);
            acc1 = fmaf(ta.w, xb.x, acc1); acc1 = fmaf(tb.x, xb.y, acc1);
            acc1 = fmaf(tb.y, xb.z, acc1); acc1 = fmaf(tb.z, xb.w, acc1);
            acc2 = fmaf(ta.z, xb.x, acc2); acc2 = fmaf(ta.w, xb.y, acc2);
            acc2 = fmaf(tb.x, xb.z, acc2); acc2 = fmaf(tb.y, xb.w, acc2);
            acc3 = fmaf(ta.y, xb.x, acc3); acc3 = fmaf(ta.z, xb.y, acc3);
            acc3 = fmaf(ta.w, xb.z, acc3); acc3 = fmaf(tb.x, xb.w, acc3);
            ta = tb;
        }
        float4 xc = *reinterpret_cast<const float4*>(xo + K0);
        acc0 = fmaf(0.5f, xc.x, acc0);
        acc1 = fmaf(0.5f, xc.y, acc1);
        acc2 = fmaf(0.5f, xc.z, acc2);
        acc3 = fmaf(0.5f, xc.w, acc3);
    }

    // dets: even thread -> 8t,8t+2,8t+4,8t+6 ; odd -> 8t+1,...
    float* o = g_filt + (b * NTH + a) * DET + 8 * t + odd;
    o[0] = acc0; o[2] = acc1; o[4] = acc2; o[6] = acc3;
}

// ---------------------------------------------------------------------------
// Kernel 2: backprojection, angle-split 6 ways. 32x32 tile, 256 threads,
// 4 pixel-rows x 4 batches per thread, scalar LDS, 3-stage cp.async ring,
// one __syncthreads per angle. Writes partial sums to g_part[z].
// pos = (j-RAD)*cos(th) - (i-RAD)*sin(th) + DET/2
// ---------------------------------------------------------------------------
__global__ void __launch_bounds__(256) backproj_kernel()
{
    __shared__ float rows[STG][B][ROWLEN];   // 24768 B
    __shared__ float cs[APB];
    __shared__ float sn[APB];

    const int z  = blockIdx.z;
    const int a0 = z * APB;
    const int j0 = blockIdx.x * 32;
    const int i0 = blockIdx.y * 32;
    const int tid = threadIdx.x;
    const int tx = tid & 31;
    const int ty = tid >> 5;             // 0..7

    if (tid < APB) {
        float ang = (float)(a0 + tid) * (PI_F / 180.0f);
        cs[tid] = cosf(ang);
        sn[tid] = sinf(ang);
    }
    // zero pad slots: STG*B*4 = 48 floats
    if (tid < STG * 16) {
        int p  = tid & 3;
        int bb = (tid >> 2) & 3;
        int st = tid >> 4;
        rows[st][bb][512 + p] = 0.0f;
    }

    // staging: thread copies 16B chunk c16 of batch rows rA and rA+2
    const int rA  = tid >> 7;            // 0 or 1
    const int c16 = tid & 127;
    const float* gA = g_filt + ((rA)     * NTH + a0) * DET + c16 * 4;
    const float* gB = g_filt + ((rA + 2) * NTH + a0) * DET + c16 * 4;
    unsigned int dA[STG], dB[STG];
    #pragma unroll
    for (int st = 0; st < STG; st++) {
        unsigned int u;
        asm("{ .reg .u64 t; cvta.to.shared.u64 t, %1; cvt.u32.u64 %0, t; }"
            : "=r"(u) : "l"((const void*)&rows[st][rA][c16 * 4]));
        dA[st] = u;
        asm("{ .reg .u64 t; cvta.to.shared.u64 t, %1; cvt.u32.u64 %0, t; }"
            : "=r"(u) : "l"((const void*)&rows[st][rA + 2][c16 * 4]));
        dB[st] = u;
    }

    // prologue: prefetch local angles 0 and 1 into stages 0 and 1
    #pragma unroll
    for (int q = 0; q < 2; q++) {
        asm volatile("cp.async.ca.shared.global [%0], [%1], 16;\n"
                     :: "r"(dA[q]), "l"(gA + q * DET) : "memory");
        asm volatile("cp.async.ca.shared.global [%0], [%1], 16;\n"
                     :: "r"(dB[q]), "l"(gB + q * DET) : "memory");
        asm volatile("cp.async.commit_group;\n" ::: "memory");
    }

    const float jf = (float)(j0 + tx - RAD);
    float xpr[4];
    #pragma unroll
    for (int r = 0; r < 4; r++) xpr[r] = (float)(i0 + ty + 8 * r - RAD);

    float acc[B][4];
    #pragma unroll
    for (int bb = 0; bb < B; bb++)
        #pragma unroll
        for (int r = 0; r < 4; r++) acc[bb][r] = 0.0f;

    int st = 0;
    for (int q = 0; q < APB; q++) {
        if (q < APB - 2) {
            asm volatile("cp.async.wait_group 1;\n" ::: "memory");
        } else {
            asm volatile("cp.async.wait_group 0;\n" ::: "memory");
        }
        __syncthreads();   // angle q staged & visible; stage (st+2)%3 free

        if (q + 2 < APB) {
            int nst = st + 2; if (nst >= STG) nst -= STG;
            asm volatile("cp.async.ca.shared.global [%0], [%1], 16;\n"
                         :: "r"(dA[nst]), "l"(gA + (q + 2) * DET) : "memory");
            asm volatile("cp.async.ca.shared.global [%0], [%1], 16;\n"
                         :: "r"(dB[nst]), "l"(gB + (q + 2) * DET) : "memory");
            asm volatile("cp.async.commit_group;\n" ::: "memory");
        }

        const float c = cs[q];
        const float s = sn[q];
        const float base = fmaf(jf, c, (float)(DET / 2));
        const float* r0 = rows[st][0];
        const float* r1 = rows[st][1];
        const float* r2 = rows[st][2];
        const float* r3 = rows[st][3];

        #pragma unroll
        for (int r = 0; r < 4; r++) {
            float pos = fmaf(-xpr[r], s, base);
            int   idx = __float2int_rd(pos);
            float w   = pos - (float)idx;
            float omw = 1.0f - w;
            // exact reference gate: contributes 0 unless 0 <= pos <= det-1
            int sel = (pos >= 0.0f && pos <= (float)(DET - 1)) ? idx : OOB;
            acc[0][r] = fmaf(omw, r0[sel], acc[0][r]);
            acc[0][r] = fmaf(w,   r0[sel + 1], acc[0][r]);
            acc[1][r] = fmaf(omw, r1[sel], acc[1][r]);
            acc[1][r] = fmaf(w,   r1[sel + 1], acc[1][r]);
            acc[2][r] = fmaf(omw, r2[sel], acc[2][r]);
            acc[2][r] = fmaf(w,   r2[sel + 1], acc[2][r]);
            acc[3][r] = fmaf(omw, r3[sel], acc[3][r]);
            acc[3][r] = fmaf(w,   r3[sel + 1], acc[3][r]);
        }

        st++; if (st >= STG) st -= STG;
    }

    const int j = j0 + tx;
    if (j < OUT) {
        float* pz = g_part + z * (B * OUT * OUT);
        #pragma unroll
        for (int bb = 0; bb < B; bb++) {
            #pragma unroll
            for (int r = 0; r < 4; r++) {
                int i = i0 + ty + 8 * r;
                if (i < OUT)
                    pz[(bb * OUT + i) * OUT + j] = acc[bb][r];
            }
        }
    }
}

// ---------------------------------------------------------------------------
// Kernel 3: combine the NSPLIT partial sums and scale.
// ---------------------------------------------------------------------------
__global__ void __launch_bounds__(256) combine_kernel(float* __restrict__ out)
{
    const int n = B * OUT * OUT;
    int idx = blockIdx.x * 256 + threadIdx.x;
    if (idx < n) {
        float v = 0.0f;
        #pragma unroll
        for (int z = 0; z < NSPLIT; z++)
            v += g_part[z * n + idx];
        out[idx] = v * (PI_F / (2.0f * (float)NTH));
    }
}

extern "C" void kernel_launch(void* const* d_in, const int* in_sizes, int n_in,
                              void* d_out, int out_size)
{
    const float* x = (const float*)d_in[0];
    float* out = (float*)d_out;

    filter_kernel<<<dim3(NTH, B), 128>>>(x);

    dim3 grid((OUT + 31) / 32, (OUT + 31) / 32, NSPLIT);   // 12 x 12 x 6
    backproj_kernel<<<grid, 256>>>();

    int n = B * OUT * OUT;
    combine_kernel<<<(n + 255) / 256, 256>>>(out);
}

// round 8
// speedup vs baseline: 2.7630x; 1.0958x over previous
#include <cuda_runtime.h>
#include <cstdint>
#include <math.h>

#define DET 512
#define NTH 180
#define B   4
#define OUT 362
#define RAD 181          // OUT//2 per reference
#define PI_F 3.14159265358979323846f

#define STG    3         // cp.async ring stages
#define NSPLIT 6         // angle splits -> 12*12*6 = 864 blocks
#define APB    30        // angles per block
#define WIN    64        // staged detector window (span <= 51 incl. safety)
#define WROW   72        // window row stride in floats (64 data + 4 zero + 4)
#define ZSLOT  64        // zero slot (64,65 zeroed)

// filtered projections with 64-float pads both ends; rows [b][a][det]
__device__ float g_fstore[64 + B * NTH * DET + 64];
// partial backprojections, layout [z][b][i][j]
__device__ float g_part[NSPLIT * B * OUT * OUT];

// ---------------------------------------------------------------------------
// Kernel 1: ramp filter as two dense parity-compressed correlations.
//   out[k] = 0.5 x[k] + sum_{d odd} g(d) x[k-d],  g(d) = -2/(pi d)^2
// T[j] = g(|2j-513|); register-shifted T window + one-iteration prefetch.
// ---------------------------------------------------------------------------
__global__ void __launch_bounds__(128) filter_kernel(const float* __restrict__ x)
{
    __shared__ __align__(16) float xe[256];
    __shared__ __align__(16) float xo[256];
    __shared__ __align__(16) float Tbuf[4 + 512 + 4];

    float* T = Tbuf + 4;

    const int a = blockIdx.x;
    const int b = blockIdx.y;
    const int tid = threadIdx.x;

    {
        int m0 = 4 * tid;
        const float* xp = x + (b * DET + m0) * NTH + a;
        float v0 = xp[0 * NTH], v1 = xp[1 * NTH];
        float v2 = xp[2 * NTH], v3 = xp[3 * NTH];
        xe[m0 / 2]     = v0;  xo[m0 / 2]     = v1;
        xe[m0 / 2 + 1] = v2;  xo[m0 / 2 + 1] = v3;
    }
    #pragma unroll
    for (int j = tid; j < 512; j += 128) {
        int d = 2 * j - 513; if (d < 0) d = -d;
        float fd = (float)d;
        T[j] = -2.0f / (PI_F * PI_F * fd * fd);
    }
    if (tid < 4) { Tbuf[tid] = 0.0f; Tbuf[516 + tid] = 0.0f; }
    __syncthreads();

    const int odd = tid >> 6;
    const int t   = tid & 63;
    const int K0  = 4 * t;

    float acc0 = 0.f, acc1 = 0.f, acc2 = 0.f, acc3 = 0.f;

    if (!odd) {
        int j0 = K0 + 256;
        float4 tb = *reinterpret_cast<const float4*>(T + j0);
        float4 ta = *reinterpret_cast<const float4*>(T + j0 - 4);
        #pragma unroll 4
        for (int M0 = 0; M0 < 256; M0 += 4, j0 -= 4) {
            float4 xb = *reinterpret_cast<const float4*>(xo + M0);
            float4 tn = *reinterpret_cast<const float4*>(T + j0 - 8); // prefetch
            acc0 = fmaf(tb.x, xb.x, acc0); acc0 = fmaf(ta.w, xb.y, acc0);
            acc0 = fmaf(ta.z, xb.z, acc0); acc0 = fmaf(ta.y, xb.w, acc0);
            acc1 = fmaf(tb.y, xb.x, acc1); acc1 = fmaf(tb.x, xb.y, acc1);
            acc1 = fmaf(ta.w, xb.z, acc1); acc1 = fmaf(ta.z, xb.w, acc1);
            acc2 = fmaf(tb.z, xb.x, acc2); acc2 = fmaf(tb.y, xb.y, acc2);
            acc2 = fmaf(tb.x, xb.z, acc2); acc2 = fmaf(ta.w, xb.w, acc2);
            acc3 = fmaf(tb.w, xb.x, acc3); acc3 = fmaf(tb.z, xb.y, acc3);
            acc3 = fmaf(tb.y, xb.z, acc3); acc3 = fmaf(tb.x, xb.w, acc3);
            tb = ta; ta = tn;
        }
        float4 xc = *reinterpret_cast<const float4*>(xe + K0);
        acc0 = fmaf(0.5f, xc.x, acc0);
        acc1 = fmaf(0.5f, xc.y, acc1);
        acc2 = fmaf(0.5f, xc.z, acc2);
        acc3 = fmaf(0.5f, xc.w, acc3);
    } else {
        int j0 = 256 - K0;
        float4 ta = *reinterpret_cast<const float4*>(T + j0 - 4);
        float4 tb = *reinterpret_cast<const float4*>(T + j0);
        #pragma unroll 4
        for (int M0 = 0; M0 < 256; M0 += 4, j0 += 4) {
            float4 xb = *reinterpret_cast<const float4*>(xe + M0);
            float4 tn = *reinterpret_cast<const float4*>(T + j0 + 4); // prefetch
            acc0 = fmaf(tb.x, xb.x, acc0); acc0 = fmaf(tb.y, xb.y, acc0);
            acc0 = fmaf(tb.z, xb.z, acc0); acc0 = fmaf(tb.w, xb.w, acc0);
            acc1 = fmaf(ta.w, xb.x, acc1); acc1 = fmaf(tb.x, xb.y, acc1);
            acc1 = fmaf(tb.y, xb.z, acc1); acc1 = fmaf(tb.z, xb.w, acc1);
            acc2 = fmaf(ta.z, xb.x, acc2); acc2 = fmaf(ta.w, xb.y, acc2);
            acc2 = fmaf(tb.x, xb.z, acc2); acc2 = fmaf(tb.y, xb.w, acc2);
            acc3 = fmaf(ta.y, xb.x, acc3); acc3 = fmaf(ta.z, xb.y, acc3);
            acc3 = fmaf(ta.w, xb.z, acc3); acc3 = fmaf(tb.x, xb.w, acc3);
            ta = tb; tb = tn;
        }
        float4 xc = *reinterpret_cast<const float4*>(xo + K0);
        acc0 = fmaf(0.5f, xc.x, acc0);
        acc1 = fmaf(0.5f, xc.y, acc1);
        acc2 = fmaf(0.5f, xc.z, acc2);
        acc3 = fmaf(0.5f, xc.w, acc3);
    }

    float* o = g_fstore + 64 + (b * NTH + a) * DET + 8 * t + odd;
    o[0] = acc0; o[2] = acc1; o[4] = acc2; o[6] = acc3;
}

// ---------------------------------------------------------------------------
// Kernel 2: backprojection, angle-split 6 ways, WINDOWED staging: only the
// 64-detector window the 32x32 tile can touch is staged per angle (1KB/angle).
// 256 threads, 4 rows x 4 batches per thread, 3-stage cp.async ring.
// pos = (j-RAD)*cos(th) - (i-RAD)*sin(th) + DET/2
// ---------------------------------------------------------------------------
__global__ void __launch_bounds__(256) backproj_kernel()
{
    __shared__ __align__(16) float win[STG][B][WROW];  // 3456 B
    __shared__ float cs[APB];
    __shared__ float sn[APB];
    __shared__ int   w0s[APB];

    const int z  = blockIdx.z;
    const int a0 = z * APB;
    const int j0 = blockIdx.x * 32;
    const int i0 = blockIdx.y * 32;
    const int tid = threadIdx.x;
    const int tx = tid & 31;
    const int ty = tid >> 5;             // 0..7

    if (tid < APB) {
        float ang = (float)(a0 + tid) * (PI_F / 180.0f);
        float c = cosf(ang);
        float s = sinf(ang);
        cs[tid] = c;
        sn[tid] = s;
        // min over tile of pos = jf*c - xf*s + 256  (s >= 0 for theta in [0,pi))
        float jlo = (float)(j0 - RAD), jhi = (float)(j0 + 31 - RAD);
        float xhi = (float)(i0 + 31 - RAD);
        float minpos = (c >= 0.0f ? c * jlo : c * jhi) - s * xhi + 256.0f;
        int w0 = (int)floorf(minpos) - 1;
        w0s[tid] = (w0 >> 2) << 2;       // align down to multiple of 4
    }
    // zero slots 64..67 of every (stage,batch) window
    if (tid < STG * 16) {
        int p  = tid & 3;
        int bb = (tid >> 2) & 3;
        int st = tid >> 4;
        win[st][bb][ZSLOT + p] = 0.0f;
    }
    __syncthreads();   // w0s needed by staging below

    // staging: threads 0..63 each copy one 16B chunk: batch=tid>>4, chunk=tid&15
    const int sbb = tid >> 4;
    const int sch = tid & 15;
    const float* fb = g_fstore + 64;
    unsigned int sdst[STG];
    #pragma unroll
    for (int st = 0; st < STG; st++) {
        unsigned int u;
        asm("{ .reg .u64 t; cvta.to.shared.u64 t, %1; cvt.u32.u64 %0, t; }"
            : "=r"(u) : "l"((const void*)&win[st][sbb & 3][sch * 4]));
        sdst[st] = u;
    }

    // prologue: prefetch local angles 0 and 1
    if (tid < 64) {
        #pragma unroll
        for (int q = 0; q < 2; q++) {
            const float* src = fb + (sbb * NTH + a0 + q) * DET + w0s[q] + sch * 4;
            asm volatile("cp.async.ca.shared.global [%0], [%1], 16;\n"
                         :: "r"(sdst[q]), "l"(src) : "memory");
        }
    }
    asm volatile("cp.async.commit_group;\n" ::: "memory");
    asm volatile("cp.async.commit_group;\n" ::: "memory");

    const float jf = (float)(j0 + tx - RAD);
    float xpr[4];
    #pragma unroll
    for (int r = 0; r < 4; r++) xpr[r] = (float)(i0 + ty + 8 * r - RAD);

    float acc[B][4];
    #pragma unroll
    for (int bb = 0; bb < B; bb++)
        #pragma unroll
        for (int r = 0; r < 4; r++) acc[bb][r] = 0.0f;

    int st = 0;
    for (int q = 0; q < APB; q++) {
        if (q < APB - 2) {
            asm volatile("cp.async.wait_group 1;\n" ::: "memory");
        } else {
            asm volatile("cp.async.wait_group 0;\n" ::: "memory");
        }
        __syncthreads();   // window q staged & visible; stage (st+2)%3 free

        {
            int nst = st + 2; if (nst >= STG) nst -= STG;
            if (q + 2 < APB && tid < 64) {
                const float* src = fb + (sbb * NTH + a0 + q + 2) * DET
                                 + w0s[q + 2] + sch * 4;
                asm volatile("cp.async.ca.shared.global [%0], [%1], 16;\n"
                             :: "r"(sdst[nst]), "l"(src) : "memory");
            }
            asm volatile("cp.async.commit_group;\n" ::: "memory");
        }

        const float c = cs[q];
        const float s = sn[q];
        const int   w0a = w0s[q];
        const float base = fmaf(jf, c, (float)(DET / 2));
        const float* r0 = win[st][0];
        const float* r1 = win[st][1];
        const float* r2 = win[st][2];
        const float* r3 = win[st][3];

        #pragma unroll
        for (int r = 0; r < 4; r++) {
            float pos = fmaf(-xpr[r], s, base);
            int   idx = __float2int_rd(pos);
            float w   = pos - (float)idx;
            float omw = 1.0f - w;
            // exact reference gate: contributes 0 unless 0 <= pos <= det-1
            int sel = (pos >= 0.0f && pos <= (float)(DET - 1)) ? (idx - w0a)
                                                               : ZSLOT;
            acc[0][r] = fmaf(omw, r0[sel], acc[0][r]);
            acc[0][r] = fmaf(w,   r0[sel + 1], acc[0][r]);
            acc[1][r] = fmaf(omw, r1[sel], acc[1][r]);
            acc[1][r] = fmaf(w,   r1[sel + 1], acc[1][r]);
            acc[2][r] = fmaf(omw, r2[sel], acc[2][r]);
            acc[2][r] = fmaf(w,   r2[sel + 1], acc[2][r]);
            acc[3][r] = fmaf(omw, r3[sel], acc[3][r]);
            acc[3][r] = fmaf(w,   r3[sel + 1], acc[3][r]);
        }

        st++; if (st >= STG) st -= STG;
    }

    const int j = j0 + tx;
    if (j < OUT) {
        float* pz = g_part + z * (B * OUT * OUT);
        #pragma unroll
        for (int bb = 0; bb < B; bb++) {
            #pragma unroll
            for (int r = 0; r < 4; r++) {
                int i = i0 + ty + 8 * r;
                if (i < OUT)
                    pz[(bb * OUT + i) * OUT + j] = acc[bb][r];
            }
        }
    }
}

// ---------------------------------------------------------------------------
// Kernel 3: combine the NSPLIT partial sums and scale.
// ---------------------------------------------------------------------------
__global__ void __launch_bounds__(256) combine_kernel(float* __restrict__ out)
{
    const int n = B * OUT * OUT;
    int idx = blockIdx.x * 256 + threadIdx.x;
    if (idx < n) {
        float v = 0.0f;
        #pragma unroll
        for (int z = 0; z < NSPLIT; z++)
            v += g_part[z * n + idx];
        out[idx] = v * (PI_F / (2.0f * (float)NTH));
    }
}

extern "C" void kernel_launch(void* const* d_in, const int* in_sizes, int n_in,
                              void* d_out, int out_size)
{
    const float* x = (const float*)d_in[0];
    float* out = (float*)d_out;

    filter_kernel<<<dim3(NTH, B), 128>>>(x);

    dim3 grid((OUT + 31) / 32, (OUT + 31) / 32, NSPLIT);   // 12 x 12 x 6
    backproj_kernel<<<grid, 256>>>();

    int n = B * OUT * OUT;
    combine_kernel<<<(n + 255) / 256, 256>>>(out);
}

// round 9
// speedup vs baseline: 2.8229x; 1.0217x over previous
#include <cuda_runtime.h>
#include <cuda_fp16.h>
#include <cstdint>
#include <math.h>

#define DET 512
#define NTH 180
#define B   4
#define OUT 362
#define RAD 181          // OUT//2 per reference
#define PI_F 3.14159265358979323846f

#define STG    3         // cp.async ring stages
#define NSPLIT 8         // angle splits -> 12*12*8 = 1152 blocks
#define APBMAX 23
#define WIN    64        // staged detector window (dets)
#define WROW   68        // window dets incl 4 zero slots
#define ZSLOT  64        // zero det slot

// filtered projections fp32, 64-float pads both ends; rows [b][a][det]
__device__ float g_fstore[64 + B * NTH * DET + 64];
// half4-interleaved projections [a][det][b], 256-half pads both ends
__device__ __align__(16) __half g_fh[256 + NTH * DET * 4 + 256];
// partial backprojections, layout [z][b][i][j]
__device__ float g_part[NSPLIT * B * OUT * OUT];

// ---------------------------------------------------------------------------
// Kernel 1: ramp filter as two dense parity-compressed correlations.
//   out[k] = 0.5 x[k] + sum_{d odd} g(d) x[k-d],  g(d) = -2/(pi d)^2
// T[j] = g(|2j-513|); register-shifted T window + one-iteration prefetch.
// ---------------------------------------------------------------------------
__global__ void __launch_bounds__(128) filter_kernel(const float* __restrict__ x)
{
    __shared__ __align__(16) float xe[256];
    __shared__ __align__(16) float xo[256];
    __shared__ __align__(16) float Tbuf[4 + 512 + 4];

    float* T = Tbuf + 4;

    const int a = blockIdx.x;
    const int b = blockIdx.y;
    const int tid = threadIdx.x;

    {
        int m0 = 4 * tid;
        const float* xp = x + (b * DET + m0) * NTH + a;
        float v0 = xp[0 * NTH], v1 = xp[1 * NTH];
        float v2 = xp[2 * NTH], v3 = xp[3 * NTH];
        xe[m0 / 2]     = v0;  xo[m0 / 2]     = v1;
        xe[m0 / 2 + 1] = v2;  xo[m0 / 2 + 1] = v3;
    }
    #pragma unroll
    for (int j = tid; j < 512; j += 128) {
        int d = 2 * j - 513; if (d < 0) d = -d;
        float fd = (float)d;
        T[j] = -2.0f / (PI_F * PI_F * fd * fd);
    }
    if (tid < 4) { Tbuf[tid] = 0.0f; Tbuf[516 + tid] = 0.0f; }
    __syncthreads();

    const int odd = tid >> 6;
    const int t   = tid & 63;
    const int K0  = 4 * t;

    float acc0 = 0.f, acc1 = 0.f, acc2 = 0.f, acc3 = 0.f;

    if (!odd) {
        int j0 = K0 + 256;
        float4 tb = *reinterpret_cast<const float4*>(T + j0);
        float4 ta = *reinterpret_cast<const float4*>(T + j0 - 4);
        #pragma unroll 4
        for (int M0 = 0; M0 < 256; M0 += 4, j0 -= 4) {
            float4 xb = *reinterpret_cast<const float4*>(xo + M0);
            float4 tn = *reinterpret_cast<const float4*>(T + j0 - 8);
            acc0 = fmaf(tb.x, xb.x, acc0); acc0 = fmaf(ta.w, xb.y, acc0);
            acc0 = fmaf(ta.z, xb.z, acc0); acc0 = fmaf(ta.y, xb.w, acc0);
            acc1 = fmaf(tb.y, xb.x, acc1); acc1 = fmaf(tb.x, xb.y, acc1);
            acc1 = fmaf(ta.w, xb.z, acc1); acc1 = fmaf(ta.z, xb.w, acc1);
            acc2 = fmaf(tb.z, xb.x, acc2); acc2 = fmaf(tb.y, xb.y, acc2);
            acc2 = fmaf(tb.x, xb.z, acc2); acc2 = fmaf(ta.w, xb.w, acc2);
            acc3 = fmaf(tb.w, xb.x, acc3); acc3 = fmaf(tb.z, xb.y, acc3);
            acc3 = fmaf(tb.y, xb.z, acc3); acc3 = fmaf(tb.x, xb.w, acc3);
            tb = ta; ta = tn;
        }
        float4 xc = *reinterpret_cast<const float4*>(xe + K0);
        acc0 = fmaf(0.5f, xc.x, acc0);
        acc1 = fmaf(0.5f, xc.y, acc1);
        acc2 = fmaf(0.5f, xc.z, acc2);
        acc3 = fmaf(0.5f, xc.w, acc3);
    } else {
        int j0 = 256 - K0;
        float4 ta = *reinterpret_cast<const float4*>(T + j0 - 4);
        float4 tb = *reinterpret_cast<const float4*>(T + j0);
        #pragma unroll 4
        for (int M0 = 0; M0 < 256; M0 += 4, j0 += 4) {
            float4 xb = *reinterpret_cast<const float4*>(xe + M0);
            float4 tn = *reinterpret_cast<const float4*>(T + j0 + 4);
            acc0 = fmaf(tb.x, xb.x, acc0); acc0 = fmaf(tb.y, xb.y, acc0);
            acc0 = fmaf(tb.z, xb.z, acc0); acc0 = fmaf(tb.w, xb.w, acc0);
            acc1 = fmaf(ta.w, xb.x, acc1); acc1 = fmaf(tb.x, xb.y, acc1);
            acc1 = fmaf(tb.y, xb.z, acc1); acc1 = fmaf(tb.z, xb.w, acc1);
            acc2 = fmaf(ta.z, xb.x, acc2); acc2 = fmaf(ta.w, xb.y, acc2);
            acc2 = fmaf(tb.x, xb.z, acc2); acc2 = fmaf(tb.y, xb.w, acc2);
            acc3 = fmaf(ta.y, xb.x, acc3); acc3 = fmaf(ta.z, xb.y, acc3);
            acc3 = fmaf(ta.w, xb.z, acc3); acc3 = fmaf(tb.x, xb.w, acc3);
            ta = tb; tb = tn;
        }
        float4 xc = *reinterpret_cast<const float4*>(xo + K0);
        acc0 = fmaf(0.5f, xc.x, acc0);
        acc1 = fmaf(0.5f, xc.y, acc1);
        acc2 = fmaf(0.5f, xc.z, acc2);
        acc3 = fmaf(0.5f, xc.w, acc3);
    }

    float* o = g_fstore + 64 + (b * NTH + a) * DET + 8 * t + odd;
    o[0] = acc0; o[2] = acc1; o[4] = acc2; o[6] = acc3;
}

// ---------------------------------------------------------------------------
// Kernel 1b: pack fp32 [b][a][det] -> half4-interleaved [a][det][b].
// Fully coalesced on both sides.
// ---------------------------------------------------------------------------
__global__ void __launch_bounds__(256) pack_kernel()
{
    const int n = NTH * DET;
    int idx = blockIdx.x * 256 + threadIdx.x;
    if (idx < n) {
        const float* f = g_fstore + 64;
        __half2 h01 = __floats2half2_rn(f[idx],         f[idx + n]);
        __half2 h23 = __floats2half2_rn(f[idx + 2 * n], f[idx + 3 * n]);
        uint2 pk;
        pk.x = *reinterpret_cast<unsigned int*>(&h01);
        pk.y = *reinterpret_cast<unsigned int*>(&h23);
        *reinterpret_cast<uint2*>(g_fh + 256 + idx * 4) = pk;
    }
}

// ---------------------------------------------------------------------------
// Kernel 2: backprojection, angle-split 8 ways (uneven 23/22), fp16 windowed
// staging: 64-det half4-interleaved window per angle (512B). 256 threads,
// 4 rows x 4 batches per thread; per row-interp 2x LDS.64 fetch all 4 batches
// at sel and sel+1. 3-stage cp.async ring, one __syncthreads per angle.
// pos = (j-RAD)*cos(th) - (i-RAD)*sin(th) + DET/2
// ---------------------------------------------------------------------------
__global__ void __launch_bounds__(256) backproj_kernel()
{
    __shared__ __align__(16) __half win[STG][WROW * 4]; // 3*544B
    __shared__ float cs[APBMAX];
    __shared__ float sn[APBMAX];
    __shared__ int   w0s[APBMAX];

    const int z  = blockIdx.z;
    const int a0 = z * 22 + (z < 4 ? z : 4);   // uneven split offsets
    const int na = 22 + (z < 4 ? 1 : 0);       // 23,23,23,23,22,22,22,22
    const int j0 = blockIdx.x * 32;
    const int i0 = blockIdx.y * 32;
    const int tid = threadIdx.x;
    const int tx = tid & 31;
    const int ty = tid >> 5;             // 0..7

    if (tid < na) {
        float ang = (float)(a0 + tid) * (PI_F / 180.0f);
        float c = cosf(ang);
        float s = sinf(ang);
        cs[tid] = c;
        sn[tid] = s;
        // min over tile of pos = jf*c - xf*s + 256   (s >= 0 on [0,pi))
        float jlo = (float)(j0 - RAD), jhi = (float)(j0 + 31 - RAD);
        float xhi = (float)(i0 + 31 - RAD);
        float minpos = (c >= 0.0f ? c * jlo : c * jhi) - s * xhi + 256.0f;
        int w0 = (int)floorf(minpos) - 1;
        w0s[tid] = (w0 >> 2) << 2;       // align down to multiple of 4
    }
    // zero det slots 64..67 (halves 256..271) of every stage
    if (tid < STG * 8) {
        int p  = tid & 7;
        int st = tid >> 3;
        reinterpret_cast<unsigned int*>(win[st])[128 + p] = 0u;
    }
    __syncthreads();   // w0s needed by staging below

    // staging: threads 0..31 copy one 16B chunk each (512B per angle)
    const int sch = tid & 31;
    const __half* fb = g_fh + 256;
    unsigned int sdst[STG];
    #pragma unroll
    for (int st = 0; st < STG; st++) {
        unsigned int u;
        asm("{ .reg .u64 t; cvta.to.shared.u64 t, %1; cvt.u32.u64 %0, t; }"
            : "=r"(u) : "l"((const void*)&win[st][sch * 8]));
        sdst[st] = u;
    }

    // prologue: prefetch local angles 0 and 1
    if (tid < 32) {
        #pragma unroll
        for (int q = 0; q < 2; q++) {
            const __half* src = fb + ((a0 + q) * DET + w0s[q]) * 4 + sch * 8;
            asm volatile("cp.async.ca.shared.global [%0], [%1], 16;\n"
                         :: "r"(sdst[q]), "l"(src) : "memory");
        }
    }
    asm volatile("cp.async.commit_group;\n" ::: "memory");
    asm volatile("cp.async.commit_group;\n" ::: "memory");

    const float jf = (float)(j0 + tx - RAD);
    float xpr[4];
    #pragma unroll
    for (int r = 0; r < 4; r++) xpr[r] = (float)(i0 + ty + 8 * r - RAD);

    float acc[B][4];
    #pragma unroll
    for (int bb = 0; bb < B; bb++)
        #pragma unroll
        for (int r = 0; r < 4; r++) acc[bb][r] = 0.0f;

    int st = 0;
    for (int q = 0; q < na; q++) {
        if (q < na - 2) {
            asm volatile("cp.async.wait_group 1;\n" ::: "memory");
        } else {
            asm volatile("cp.async.wait_group 0;\n" ::: "memory");
        }
        __syncthreads();   // window q staged & visible; stage (st+2)%3 free

        {
            int nst = st + 2; if (nst >= STG) nst -= STG;
            if (q + 2 < na && tid < 32) {
                const __half* src = fb + ((a0 + q + 2) * DET + w0s[q + 2]) * 4
                                  + sch * 8;
                asm volatile("cp.async.ca.shared.global [%0], [%1], 16;\n"
                             :: "r"(sdst[nst]), "l"(src) : "memory");
            }
            asm volatile("cp.async.commit_group;\n" ::: "memory");
        }

        const float c = cs[q];
        const float s = sn[q];
        const int   w0a = w0s[q];
        const float base = fmaf(jf, c, (float)(DET / 2));
        const __half* wp = win[st];

        #pragma unroll
        for (int r = 0; r < 4; r++) {
            float pos = fmaf(-xpr[r], s, base);
            int   idx = __float2int_rd(pos);
            float w   = pos - (float)idx;
            float omw = 1.0f - w;
            // exact reference gate: contributes 0 unless 0 <= pos <= det-1
            int sel = (pos >= 0.0f && pos <= (float)(DET - 1)) ? (idx - w0a)
                                                               : ZSLOT;
            uint2 qa = *reinterpret_cast<const uint2*>(wp + sel * 4);
            uint2 qb = *reinterpret_cast<const uint2*>(wp + sel * 4 + 4);
            float2 a01 = __half22float2(*reinterpret_cast<__half2*>(&qa.x));
            float2 a23 = __half22float2(*reinterpret_cast<__half2*>(&qa.y));
            float2 b01 = __half22float2(*reinterpret_cast<__half2*>(&qb.x));
            float2 b23 = __half22float2(*reinterpret_cast<__half2*>(&qb.y));
            acc[0][r] = fmaf(omw, a01.x, acc[0][r]);
            acc[0][r] = fmaf(w,   b01.x, acc[0][r]);
            acc[1][r] = fmaf(omw, a01.y, acc[1][r]);
            acc[1][r] = fmaf(w,   b01.y, acc[1][r]);
            acc[2][r] = fmaf(omw, a23.x, acc[2][r]);
            acc[2][r] = fmaf(w,   b23.x, acc[2][r]);
            acc[3][r] = fmaf(omw, a23.y, acc[3][r]);
            acc[3][r] = fmaf(w,   b23.y, acc[3][r]);
        }

        st++; if (st >= STG) st -= STG;
    }

    const int j = j0 + tx;
    if (j < OUT) {
        float* pz = g_part + z * (B * OUT * OUT);
        #pragma unroll
        for (int bb = 0; bb < B; bb++) {
            #pragma unroll
            for (int r = 0; r < 4; r++) {
                int i = i0 + ty + 8 * r;
                if (i < OUT)
                    pz[(bb * OUT + i) * OUT + j] = acc[bb][r];
            }
        }
    }
}

// ---------------------------------------------------------------------------
// Kernel 3: combine the NSPLIT partial sums and scale.
// ---------------------------------------------------------------------------
__global__ void __launch_bounds__(256) combine_kernel(float* __restrict__ out)
{
    const int n = B * OUT * OUT;
    int idx = blockIdx.x * 256 + threadIdx.x;
    if (idx < n) {
        float v = 0.0f;
        #pragma unroll
        for (int z = 0; z < NSPLIT; z++)
            v += g_part[z * n + idx];
        out[idx] = v * (PI_F / (2.0f * (float)NTH));
    }
}

extern "C" void kernel_launch(void* const* d_in, const int* in_sizes, int n_in,
                              void* d_out, int out_size)
{
    const float* x = (const float*)d_in[0];
    float* out = (float*)d_out;

    filter_kernel<<<dim3(NTH, B), 128>>>(x);

    int np = NTH * DET;
    pack_kernel<<<(np + 255) / 256, 256>>>();

    dim3 grid((OUT + 31) / 32, (OUT + 31) / 32, NSPLIT);   // 12 x 12 x 8
    backproj_kernel<<<grid, 256>>>();

    int n = B * OUT * OUT;
    combine_kernel<<<(n + 255) / 256, 256>>>(out);
}

// round 10
// speedup vs baseline: 3.1859x; 1.1286x over previous
#include <cuda_runtime.h>
#include <cuda_fp16.h>
#include <cstdint>
#include <math.h>

#define DET 512
#define NTH 180
#define B   4
#define OUT 362
#define RAD 181          // OUT//2 per reference
#define PI_F 3.14159265358979323846f

#define STG    3         // cp.async ring stages
#define NSPLIT 8         // angle splits -> 12*12*8 = 1152 blocks
#define APBMAX 23
#define WIN    64        // staged detector window (dets)
#define WROW   68        // window dets incl 4 zero slots
#define ZSLOT  64        // zero det slot

// filtered projections fp32, 64-float pads both ends; rows [b][a][det]
__device__ float g_fstore[64 + B * NTH * DET + 64];
// half4-interleaved projections [a][det][b], 256-half pads both ends
__device__ __align__(16) __half g_fh[256 + NTH * DET * 4 + 256];

// ---------------------------------------------------------------------------
// Kernel 0: zero the output (it is atomically accumulated into).
// ---------------------------------------------------------------------------
__global__ void __launch_bounds__(256) zero_kernel(float* __restrict__ out)
{
    const int n4 = (B * OUT * OUT) / 4;   // 524176/4 = 131044
    int idx = blockIdx.x * 256 + threadIdx.x;
    if (idx < n4)
        reinterpret_cast<float4*>(out)[idx] = make_float4(0.f, 0.f, 0.f, 0.f);
}

// ---------------------------------------------------------------------------
// Kernel 1: ramp filter as two dense parity-compressed correlations.
//   out[k] = 0.5 x[k] + sum_{d odd} g(d) x[k-d],  g(d) = -2/(pi d)^2
// T[j] = g(|2j-513|); register-shifted T window + one-iteration prefetch.
// ---------------------------------------------------------------------------
__global__ void __launch_bounds__(128) filter_kernel(const float* __restrict__ x)
{
    __shared__ __align__(16) float xe[256];
    __shared__ __align__(16) float xo[256];
    __shared__ __align__(16) float Tbuf[4 + 512 + 4];

    float* T = Tbuf + 4;

    const int a = blockIdx.x;
    const int b = blockIdx.y;
    const int tid = threadIdx.x;

    {
        int m0 = 4 * tid;
        const float* xp = x + (b * DET + m0) * NTH + a;
        float v0 = xp[0 * NTH], v1 = xp[1 * NTH];
        float v2 = xp[2 * NTH], v3 = xp[3 * NTH];
        xe[m0 / 2]     = v0;  xo[m0 / 2]     = v1;
        xe[m0 / 2 + 1] = v2;  xo[m0 / 2 + 1] = v3;
    }
    #pragma unroll
    for (int j = tid; j < 512; j += 128) {
        int d = 2 * j - 513; if (d < 0) d = -d;
        float fd = (float)d;
        T[j] = -2.0f / (PI_F * PI_F * fd * fd);
    }
    if (tid < 4) { Tbuf[tid] = 0.0f; Tbuf[516 + tid] = 0.0f; }
    __syncthreads();

    const int odd = tid >> 6;
    const int t   = tid & 63;
    const int K0  = 4 * t;

    float acc0 = 0.f, acc1 = 0.f, acc2 = 0.f, acc3 = 0.f;

    if (!odd) {
        int j0 = K0 + 256;
        float4 tb = *reinterpret_cast<const float4*>(T + j0);
        float4 ta = *reinterpret_cast<const float4*>(T + j0 - 4);
        #pragma unroll 4
        for (int M0 = 0; M0 < 256; M0 += 4, j0 -= 4) {
            float4 xb = *reinterpret_cast<const float4*>(xo + M0);
            float4 tn = *reinterpret_cast<const float4*>(T + j0 - 8);
            acc0 = fmaf(tb.x, xb.x, acc0); acc0 = fmaf(ta.w, xb.y, acc0);
            acc0 = fmaf(ta.z, xb.z, acc0); acc0 = fmaf(ta.y, xb.w, acc0);
            acc1 = fmaf(tb.y, xb.x, acc1); acc1 = fmaf(tb.x, xb.y, acc1);
            acc1 = fmaf(ta.w, xb.z, acc1); acc1 = fmaf(ta.z, xb.w, acc1);
            acc2 = fmaf(tb.z, xb.x, acc2); acc2 = fmaf(tb.y, xb.y, acc2);
            acc2 = fmaf(tb.x, xb.z, acc2); acc2 = fmaf(ta.w, xb.w, acc2);
            acc3 = fmaf(tb.w, xb.x, acc3); acc3 = fmaf(tb.z, xb.y, acc3);
            acc3 = fmaf(tb.y, xb.z, acc3); acc3 = fmaf(tb.x, xb.w, acc3);
            tb = ta; ta = tn;
        }
        float4 xc = *reinterpret_cast<const float4*>(xe + K0);
        acc0 = fmaf(0.5f, xc.x, acc0);
        acc1 = fmaf(0.5f, xc.y, acc1);
        acc2 = fmaf(0.5f, xc.z, acc2);
        acc3 = fmaf(0.5f, xc.w, acc3);
    } else {
        int j0 = 256 - K0;
        float4 ta = *reinterpret_cast<const float4*>(T + j0 - 4);
        float4 tb = *reinterpret_cast<const float4*>(T + j0);
        #pragma unroll 4
        for (int M0 = 0; M0 < 256; M0 += 4, j0 += 4) {
            float4 xb = *reinterpret_cast<const float4*>(xe + M0);
            float4 tn = *reinterpret_cast<const float4*>(T + j0 + 4);
            acc0 = fmaf(tb.x, xb.x, acc0); acc0 = fmaf(tb.y, xb.y, acc0);
            acc0 = fmaf(tb.z, xb.z, acc0); acc0 = fmaf(tb.w, xb.w, acc0);
            acc1 = fmaf(ta.w, xb.x, acc1); acc1 = fmaf(tb.x, xb.y, acc1);
            acc1 = fmaf(tb.y, xb.z, acc1); acc1 = fmaf(tb.z, xb.w, acc1);
            acc2 = fmaf(ta.z, xb.x, acc2); acc2 = fmaf(ta.w, xb.y, acc2);
            acc2 = fmaf(tb.x, xb.z, acc2); acc2 = fmaf(tb.y, xb.w, acc2);
            acc3 = fmaf(ta.y, xb.x, acc3); acc3 = fmaf(ta.z, xb.y, acc3);
            acc3 = fmaf(ta.w, xb.z, acc3); acc3 = fmaf(tb.x, xb.w, acc3);
            ta = tb; tb = tn;
        }
        float4 xc = *reinterpret_cast<const float4*>(xo + K0);
        acc0 = fmaf(0.5f, xc.x, acc0);
        acc1 = fmaf(0.5f, xc.y, acc1);
        acc2 = fmaf(0.5f, xc.z, acc2);
        acc3 = fmaf(0.5f, xc.w, acc3);
    }

    float* o = g_fstore + 64 + (b * NTH + a) * DET + 8 * t + odd;
    o[0] = acc0; o[2] = acc1; o[4] = acc2; o[6] = acc3;
}

// ---------------------------------------------------------------------------
// Kernel 1b: pack fp32 [b][a][det] -> half4-interleaved [a][det][b].
// ---------------------------------------------------------------------------
__global__ void __launch_bounds__(256) pack_kernel()
{
    const int n = NTH * DET;
    int idx = blockIdx.x * 256 + threadIdx.x;
    if (idx < n) {
        const float* f = g_fstore + 64;
        __half2 h01 = __floats2half2_rn(f[idx],         f[idx + n]);
        __half2 h23 = __floats2half2_rn(f[idx + 2 * n], f[idx + 3 * n]);
        uint2 pk;
        pk.x = *reinterpret_cast<unsigned int*>(&h01);
        pk.y = *reinterpret_cast<unsigned int*>(&h23);
        *reinterpret_cast<uint2*>(g_fh + 256 + idx * 4) = pk;
    }
}

// ---------------------------------------------------------------------------
// Kernel 2: backprojection, angle-split 8 ways (23/22), fp16 windowed staging,
// half-domain lerp (hfma2), fp32 accumulation, RED.ADD into out.
// pos = (j-RAD)*cos(th) - (i-RAD)*sin(th) + DET/2
// ---------------------------------------------------------------------------
__global__ void __launch_bounds__(256) backproj_kernel(float* __restrict__ out)
{
    __shared__ __align__(16) __half win[STG][WROW * 4]; // 3*544B
    __shared__ float cs[APBMAX];
    __shared__ float sn[APBMAX];
    __shared__ int   w0s[APBMAX];

    const int z  = blockIdx.z;
    const int a0 = z * 22 + (z < 4 ? z : 4);   // uneven split offsets
    const int na = 22 + (z < 4 ? 1 : 0);       // 23,23,23,23,22,22,22,22
    const int j0 = blockIdx.x * 32;
    const int i0 = blockIdx.y * 32;
    const int tid = threadIdx.x;
    const int tx = tid & 31;
    const int ty = tid >> 5;             // 0..7

    if (tid < na) {
        float ang = (float)(a0 + tid) * (PI_F / 180.0f);
        float c = cosf(ang);
        float s = sinf(ang);
        cs[tid] = c;
        sn[tid] = s;
        // min over tile of pos = jf*c - xf*s + 256   (s >= 0 on [0,pi))
        float jlo = (float)(j0 - RAD), jhi = (float)(j0 + 31 - RAD);
        float xhi = (float)(i0 + 31 - RAD);
        float minpos = (c >= 0.0f ? c * jlo : c * jhi) - s * xhi + 256.0f;
        int w0 = (int)floorf(minpos) - 1;
        w0s[tid] = (w0 >> 2) << 2;       // align down to multiple of 4
    }
    // zero det slots 64..67 (halves 256..271) of every stage
    if (tid < STG * 8) {
        int p  = tid & 7;
        int st = tid >> 3;
        reinterpret_cast<unsigned int*>(win[st])[128 + p] = 0u;
    }
    __syncthreads();   // w0s needed by staging below

    // staging: threads 0..31 copy one 16B chunk each (512B per angle)
    const int sch = tid & 31;
    const __half* fb = g_fh + 256;
    unsigned int sdst[STG];
    #pragma unroll
    for (int st = 0; st < STG; st++) {
        unsigned int u;
        asm("{ .reg .u64 t; cvta.to.shared.u64 t, %1; cvt.u32.u64 %0, t; }"
            : "=r"(u) : "l"((const void*)&win[st][sch * 8]));
        sdst[st] = u;
    }

    // prologue: prefetch local angles 0 and 1
    if (tid < 32) {
        #pragma unroll
        for (int q = 0; q < 2; q++) {
            const __half* src = fb + ((a0 + q) * DET + w0s[q]) * 4 + sch * 8;
            asm volatile("cp.async.ca.shared.global [%0], [%1], 16;\n"
                         :: "r"(sdst[q]), "l"(src) : "memory");
        }
    }
    asm volatile("cp.async.commit_group;\n" ::: "memory");
    asm volatile("cp.async.commit_group;\n" ::: "memory");

    const float jf = (float)(j0 + tx - RAD);
    float xpr[4];
    #pragma unroll
    for (int r = 0; r < 4; r++) xpr[r] = (float)(i0 + ty + 8 * r - RAD);

    float acc[B][4];
    #pragma unroll
    for (int bb = 0; bb < B; bb++)
        #pragma unroll
        for (int r = 0; r < 4; r++) acc[bb][r] = 0.0f;

    int st = 0;
    for (int q = 0; q < na; q++) {
        if (q < na - 2) {
            asm volatile("cp.async.wait_group 1;\n" ::: "memory");
        } else {
            asm volatile("cp.async.wait_group 0;\n" ::: "memory");
        }
        __syncthreads();   // window q staged & visible; stage (st+2)%3 free

        {
            int nst = st + 2; if (nst >= STG) nst -= STG;
            if (q + 2 < na && tid < 32) {
                const __half* src = fb + ((a0 + q + 2) * DET + w0s[q + 2]) * 4
                                  + sch * 8;
                asm volatile("cp.async.ca.shared.global [%0], [%1], 16;\n"
                             :: "r"(sdst[nst]), "l"(src) : "memory");
            }
            asm volatile("cp.async.commit_group;\n" ::: "memory");
        }

        const float c = cs[q];
        const float s = sn[q];
        const int   w0a = w0s[q];
        const float base = fmaf(jf, c, (float)(DET / 2));
        const __half* wp = win[st];

        #pragma unroll
        for (int r = 0; r < 4; r++) {
            float pos = fmaf(-xpr[r], s, base);
            int   idx = __float2int_rd(pos);
            float w   = pos - (float)idx;
            // exact reference gate: contributes 0 unless 0 <= pos <= det-1
            int sel = (pos >= 0.0f && pos <= (float)(DET - 1)) ? (idx - w0a)
                                                               : ZSLOT;
            uint2 qa = *reinterpret_cast<const uint2*>(wp + sel * 4);
            uint2 qb = *reinterpret_cast<const uint2*>(wp + sel * 4 + 4);
            __half2 w2 = __float2half2_rn(w);
            __half2 qa01 = *reinterpret_cast<__half2*>(&qa.x);
            __half2 qa23 = *reinterpret_cast<__half2*>(&qa.y);
            __half2 qb01 = *reinterpret_cast<__half2*>(&qb.x);
            __half2 qb23 = *reinterpret_cast<__half2*>(&qb.y);
            __half2 v01 = __hfma2(w2, __hsub2(qb01, qa01), qa01);
            __half2 v23 = __hfma2(w2, __hsub2(qb23, qa23), qa23);
            float2 f01 = __half22float2(v01);
            float2 f23 = __half22float2(v23);
            acc[0][r] += f01.x;
            acc[1][r] += f01.y;
            acc[2][r] += f23.x;
            acc[3][r] += f23.y;
        }

        st++; if (st >= STG) st -= STG;
    }

    const float scale = PI_F / (2.0f * (float)NTH);
    const int j = j0 + tx;
    if (j < OUT) {
        #pragma unroll
        for (int bb = 0; bb < B; bb++) {
            #pragma unroll
            for (int r = 0; r < 4; r++) {
                int i = i0 + ty + 8 * r;
                if (i < OUT)
                    atomicAdd(&out[(bb * OUT + i) * OUT + j], acc[bb][r] * scale);
            }
        }
    }
}

extern "C" void kernel_launch(void* const* d_in, const int* in_sizes, int n_in,
                              void* d_out, int out_size)
{
    const float* x = (const float*)d_in[0];
    float* out = (float*)d_out;

    int n4 = (B * OUT * OUT) / 4;
    zero_kernel<<<(n4 + 255) / 256, 256>>>(out);

    filter_kernel<<<dim3(NTH, B), 128>>>(x);

    int np = NTH * DET;
    pack_kernel<<<(np + 255) / 256, 256>>>();

    dim3 grid((OUT + 31) / 32, (OUT + 31) / 32, NSPLIT);   // 12 x 12 x 8
    backproj_kernel<<<grid, 256>>>(out);
}

// round 11
// speedup vs baseline: 3.3547x; 1.0530x over previous
#include <cuda_runtime.h>
#include <cuda_fp16.h>
#include <cstdint>
#include <math.h>

#define DET 512
#define NTH 180
#define B   4
#define OUT 362
#define RAD 181          // OUT//2 per reference
#define PI_F 3.14159265358979323846f

#define PSTG   3         // cp.async ring PAIR stages (2 angles each)
#define NSPLIT 8         // angle splits: {24,24,22,22,22,22,22,22}
#define APBMAX 24
#define WIN    64        // staged detector window (dets)
#define WROW   68        // window dets incl 4 zero slots
#define ZSLOT  64        // zero det slot
#define GATE_U 0x43FF8000u   // bits of 511.0f

// filtered projection partials (two tap-halves), [z][b][a][det]
__device__ float g_fstore[2][B * NTH * DET];
// half4-interleaved projections [a][det][b], 256-half pads both ends
__device__ __align__(16) __half g_fh[256 + NTH * DET * 4 + 256];

// ---------------------------------------------------------------------------
// Kernel 0: zero the output (it is atomically accumulated into).
// ---------------------------------------------------------------------------
__global__ void __launch_bounds__(256) zero_kernel(float* __restrict__ out)
{
    const int n4 = (B * OUT * OUT) / 4;
    int idx = blockIdx.x * 256 + threadIdx.x;
    if (idx < n4)
        reinterpret_cast<float4*>(out)[idx] = make_float4(0.f, 0.f, 0.f, 0.f);
}

// ---------------------------------------------------------------------------
// Kernel 1: ramp filter, parity-compressed, TAP-SPLIT 2 ways (blockIdx.z):
// each block sums 32 of the 64 4-tap groups; pack adds the two partials.
//   out[k] = 0.5 x[k] + sum_{d odd} g(d) x[k-d],  g(d) = -2/(pi d)^2
// ---------------------------------------------------------------------------
__global__ void __launch_bounds__(128) filter_kernel(const float* __restrict__ x)
{
    __shared__ __align__(16) float xe[256];
    __shared__ __align__(16) float xo[256];
    __shared__ __align__(16) float Tbuf[4 + 512 + 4];

    float* T = Tbuf + 4;

    const int a = blockIdx.x;
    const int b = blockIdx.y;
    const int z = blockIdx.z;          // tap half
    const int tid = threadIdx.x;

    {
        int m0 = 4 * tid;
        const float* xp = x + (b * DET + m0) * NTH + a;
        float v0 = xp[0 * NTH], v1 = xp[1 * NTH];
        float v2 = xp[2 * NTH], v3 = xp[3 * NTH];
        xe[m0 / 2]     = v0;  xo[m0 / 2]     = v1;
        xe[m0 / 2 + 1] = v2;  xo[m0 / 2 + 1] = v3;
    }
    #pragma unroll
    for (int j = tid; j < 512; j += 128) {
        int d = 2 * j - 513; if (d < 0) d = -d;
        float fd = (float)d;
        T[j] = -2.0f / (PI_F * PI_F * fd * fd);
    }
    if (tid < 4) { Tbuf[tid] = 0.0f; Tbuf[516 + tid] = 0.0f; }
    __syncthreads();

    const int odd = tid >> 6;
    const int t   = tid & 63;
    const int K0  = 4 * t;
    const int M0_beg = z * 128;
    const int M0_end = M0_beg + 128;

    float acc0 = 0.f, acc1 = 0.f, acc2 = 0.f, acc3 = 0.f;

    if (!odd) {
        int j0 = K0 + 256 - M0_beg;
        float4 tb = *reinterpret_cast<const float4*>(T + j0);
        float4 ta = *reinterpret_cast<const float4*>(T + j0 - 4);
        #pragma unroll 4
        for (int M0 = M0_beg; M0 < M0_end; M0 += 4, j0 -= 4) {
            float4 xb = *reinterpret_cast<const float4*>(xo + M0);
            float4 tn = *reinterpret_cast<const float4*>(T + j0 - 8);
            acc0 = fmaf(tb.x, xb.x, acc0); acc0 = fmaf(ta.w, xb.y, acc0);
            acc0 = fmaf(ta.z, xb.z, acc0); acc0 = fmaf(ta.y, xb.w, acc0);
            acc1 = fmaf(tb.y, xb.x, acc1); acc1 = fmaf(tb.x, xb.y, acc1);
            acc1 = fmaf(ta.w, xb.z, acc1); acc1 = fmaf(ta.z, xb.w, acc1);
            acc2 = fmaf(tb.z, xb.x, acc2); acc2 = fmaf(tb.y, xb.y, acc2);
            acc2 = fmaf(tb.x, xb.z, acc2); acc2 = fmaf(ta.w, xb.w, acc2);
            acc3 = fmaf(tb.w, xb.x, acc3); acc3 = fmaf(tb.z, xb.y, acc3);
            acc3 = fmaf(tb.y, xb.z, acc3); acc3 = fmaf(tb.x, xb.w, acc3);
            tb = ta; ta = tn;
        }
        if (z == 0) {
            float4 xc = *reinterpret_cast<const float4*>(xe + K0);
            acc0 = fmaf(0.5f, xc.x, acc0);
            acc1 = fmaf(0.5f, xc.y, acc1);
            acc2 = fmaf(0.5f, xc.z, acc2);
            acc3 = fmaf(0.5f, xc.w, acc3);
        }
    } else {
        int j0 = 256 - K0 + M0_beg;
        float4 ta = *reinterpret_cast<const float4*>(T + j0 - 4);
        float4 tb = *reinterpret_cast<const float4*>(T + j0);
        #pragma unroll 4
        for (int M0 = M0_beg; M0 < M0_end; M0 += 4, j0 += 4) {
            float4 xb = *reinterpret_cast<const float4*>(xe + M0);
            float4 tn = *reinterpret_cast<const float4*>(T + j0 + 4);
            acc0 = fmaf(tb.x, xb.x, acc0); acc0 = fmaf(tb.y, xb.y, acc0);
            acc0 = fmaf(tb.z, xb.z, acc0); acc0 = fmaf(tb.w, xb.w, acc0);
            acc1 = fmaf(ta.w, xb.x, acc1); acc1 = fmaf(tb.x, xb.y, acc1);
            acc1 = fmaf(tb.y, xb.z, acc1); acc1 = fmaf(tb.z, xb.w, acc1);
            acc2 = fmaf(ta.z, xb.x, acc2); acc2 = fmaf(ta.w, xb.y, acc2);
            acc2 = fmaf(tb.x, xb.z, acc2); acc2 = fmaf(tb.y, xb.w, acc2);
            acc3 = fmaf(ta.y, xb.x, acc3); acc3 = fmaf(ta.z, xb.y, acc3);
            acc3 = fmaf(ta.w, xb.z, acc3); acc3 = fmaf(tb.x, xb.w, acc3);
            ta = tb; tb = tn;
        }
        if (z == 0) {
            float4 xc = *reinterpret_cast<const float4*>(xo + K0);
            acc0 = fmaf(0.5f, xc.x, acc0);
            acc1 = fmaf(0.5f, xc.y, acc1);
            acc2 = fmaf(0.5f, xc.z, acc2);
            acc3 = fmaf(0.5f, xc.w, acc3);
        }
    }

    float* o = g_fstore[z] + (b * NTH + a) * DET + 8 * t + odd;
    o[0] = acc0; o[2] = acc1; o[4] = acc2; o[6] = acc3;
}

// ---------------------------------------------------------------------------
// Kernel 1b: pack (partial0 + partial1) fp32 -> half4-interleaved [a][det][b].
// ---------------------------------------------------------------------------
__global__ void __launch_bounds__(256) pack_kernel()
{
    const int n = NTH * DET;
    int idx = blockIdx.x * 256 + threadIdx.x;
    if (idx < n) {
        const float* f0 = g_fstore[0];
        const float* f1 = g_fstore[1];
        __half2 h01 = __floats2half2_rn(f0[idx]         + f1[idx],
                                        f0[idx + n]     + f1[idx + n]);
        __half2 h23 = __floats2half2_rn(f0[idx + 2 * n] + f1[idx + 2 * n],
                                        f0[idx + 3 * n] + f1[idx + 3 * n]);
        uint2 pk;
        pk.x = *reinterpret_cast<unsigned int*>(&h01);
        pk.y = *reinterpret_cast<unsigned int*>(&h23);
        *reinterpret_cast<uint2*>(g_fh + 256 + idx * 4) = pk;
    }
}

// ---------------------------------------------------------------------------
// Kernel 2: backprojection, angle-split 8 ways (24/22, all even), fp16
// windowed PAIR staging (2 angles per ring slot -> one barrier per 2 angles),
// uint-compare range gate, half lerp, fp32 accumulation, RED.ADD into out.
// pos = (j-RAD)*cos(th) - (i-RAD)*sin(th) + DET/2
// ---------------------------------------------------------------------------
__global__ void __launch_bounds__(256) backproj_kernel(float* __restrict__ out)
{
    __shared__ __align__(16) __half win[PSTG][2][WROW * 4]; // 3264 B
    __shared__ float cs[APBMAX];
    __shared__ float sn[APBMAX];
    __shared__ int   w0s[APBMAX];

    const int z  = blockIdx.z;
    const int a0 = (z < 2) ? z * 24 : 48 + (z - 2) * 22;
    const int na = (z < 2) ? 24 : 22;            // all even
    const int npairs = na >> 1;
    const int j0 = blockIdx.x * 32;
    const int i0 = blockIdx.y * 32;
    const int tid = threadIdx.x;
    const int tx = tid & 31;
    const int ty = tid >> 5;             // 0..7

    if (tid < na) {
        float ang = (float)(a0 + tid) * (PI_F / 180.0f);
        float c = cosf(ang);
        float s = sinf(ang);
        cs[tid] = c;
        sn[tid] = s;
        // min over tile of pos = jf*c - xf*s + 256   (s >= 0 on [0,pi))
        float jlo = (float)(j0 - RAD), jhi = (float)(j0 + 31 - RAD);
        float xhi = (float)(i0 + 31 - RAD);
        float minpos = (c >= 0.0f ? c * jlo : c * jhi) - s * xhi + 256.0f;
        int w0 = (int)floorf(minpos) - 1;
        w0s[tid] = (w0 >> 2) << 2;       // align down to multiple of 4
    }
    // zero det slots 64..67 (uints 128..135) of all PSTG*2 windows
    if (tid < PSTG * 2 * 8) {
        int p = tid & 7;
        int w = tid >> 3;                // 0..5
        unsigned int* wu = reinterpret_cast<unsigned int*>(&win[0][0][0]);
        wu[w * (WROW * 4 / 2) + 128 + p] = 0u;
    }
    __syncthreads();   // w0s needed by staging below

    // staging: threads 0..63 copy 16B each; hw = angle-in-pair, sch = chunk
    const int hw  = (tid >> 5) & 1;
    const int sch = tid & 31;
    const __half* fb = g_fh + 256;
    unsigned int sdst[PSTG];
    #pragma unroll
    for (int st = 0; st < PSTG; st++) {
        unsigned int u;
        asm("{ .reg .u64 t; cvta.to.shared.u64 t, %1; cvt.u32.u64 %0, t; }"
            : "=r"(u) : "l"((const void*)&win[st][hw][sch * 8]));
        sdst[st] = u;
    }

    // prologue: prefetch pairs 0 and 1 into stages 0 and 1
    if (tid < 64) {
        #pragma unroll
        for (int p = 0; p < 2; p++) {
            int q = 2 * p + hw;
            const __half* src = fb + ((a0 + q) * DET + w0s[q]) * 4 + sch * 8;
            asm volatile("cp.async.ca.shared.global [%0], [%1], 16;\n"
                         :: "r"(sdst[p]), "l"(src) : "memory");
        }
    }
    asm volatile("cp.async.commit_group;\n" ::: "memory");
    asm volatile("cp.async.commit_group;\n" ::: "memory");

    const float jf = (float)(j0 + tx - RAD);
    float xpr[4];
    #pragma unroll
    for (int r = 0; r < 4; r++) xpr[r] = (float)(i0 + ty + 8 * r - RAD);

    float acc[B][4];
    #pragma unroll
    for (int bb = 0; bb < B; bb++)
        #pragma unroll
        for (int r = 0; r < 4; r++) acc[bb][r] = 0.0f;

    int st = 0;
    for (int p = 0; p < npairs; p++) {
        if (p < npairs - 1) {
            asm volatile("cp.async.wait_group 1;\n" ::: "memory");
        } else {
            asm volatile("cp.async.wait_group 0;\n" ::: "memory");
        }
        __syncthreads();   // pair p staged & visible; stage (st+2)%3 free

        {
            int nst = st + 2; if (nst >= PSTG) nst -= PSTG;
            if (p + 2 < npairs && tid < 64) {
                int q = 2 * (p + 2) + hw;
                const __half* src = fb + ((a0 + q) * DET + w0s[q]) * 4
                                  + sch * 8;
                asm volatile("cp.async.ca.shared.global [%0], [%1], 16;\n"
                             :: "r"(sdst[nst]), "l"(src) : "memory");
            }
            asm volatile("cp.async.commit_group;\n" ::: "memory");
        }

        #pragma unroll
        for (int h = 0; h < 2; h++) {
            const int q = 2 * p + h;
            const float c = cs[q];
            const float s = sn[q];
            const int   w0a = w0s[q];
            const float base = fmaf(jf, c, (float)(DET / 2));
            const __half* wp = win[st][h];

            #pragma unroll
            for (int r = 0; r < 4; r++) {
                float pos = fmaf(-xpr[r], s, base);
                int   idx = __float2int_rd(pos);
                float w   = pos - (float)idx;
                // gate: pos in [0,511] <=> float bits <= bits(511.0f)
                int sel = (__float_as_uint(pos) <= GATE_U) ? (idx - w0a)
                                                           : ZSLOT;
                uint2 qa = *reinterpret_cast<const uint2*>(wp + sel * 4);
                uint2 qb = *reinterpret_cast<const uint2*>(wp + sel * 4 + 4);
                __half2 w2 = __float2half2_rn(w);
                __half2 qa01 = *reinterpret_cast<__half2*>(&qa.x);
                __half2 qa23 = *reinterpret_cast<__half2*>(&qa.y);
                __half2 qb01 = *reinterpret_cast<__half2*>(&qb.x);
                __half2 qb23 = *reinterpret_cast<__half2*>(&qb.y);
                __half2 v01 = __hfma2(w2, __hsub2(qb01, qa01), qa01);
                __half2 v23 = __hfma2(w2, __hsub2(qb23, qa23), qa23);
                float2 f01 = __half22float2(v01);
                float2 f23 = __half22float2(v23);
                acc[0][r] += f01.x;
                acc[1][r] += f01.y;
                acc[2][r] += f23.x;
                acc[3][r] += f23.y;
            }
        }

        st++; if (st >= PSTG) st -= PSTG;
    }

    const float scale = PI_F / (2.0f * (float)NTH);
    const int j = j0 + tx;
    if (j < OUT) {
        #pragma unroll
        for (int bb = 0; bb < B; bb++) {
            #pragma unroll
            for (int r = 0; r < 4; r++) {
                int i = i0 + ty + 8 * r;
                if (i < OUT)
                    atomicAdd(&out[(bb * OUT + i) * OUT + j], acc[bb][r] * scale);
            }
        }
    }
}

extern "C" void kernel_launch(void* const* d_in, const int* in_sizes, int n_in,
                              void* d_out, int out_size)
{
    const float* x = (const float*)d_in[0];
    float* out = (float*)d_out;

    int n4 = (B * OUT * OUT) / 4;
    zero_kernel<<<(n4 + 255) / 256, 256>>>(out);

    filter_kernel<<<dim3(NTH, B, 2), 128>>>(x);

    int np = NTH * DET;
    pack_kernel<<<(np + 255) / 256, 256>>>();

    dim3 grid((OUT + 31) / 32, (OUT + 31) / 32, NSPLIT);   // 12 x 12 x 8
    backproj_kernel<<<grid, 256>>>(out);
}

// round 12
// speedup vs baseline: 3.5177x; 1.0486x over previous
#include <cuda_runtime.h>
#include <cuda_fp16.h>
#include <cstdint>
#include <math.h>

#define DET 512
#define NTH 180
#define B   4
#define OUT 362
#define RAD 181          // OUT//2 per reference
#define PI_F 3.14159265358979323846f

#define PSTG   3         // cp.async ring PAIR stages (2 angles each)
#define NSPLIT 6         // angle splits: 6 x 30 -> 864 blocks (one wave @6/SM)
#define APB    30        // angles per block (even)
#define WIN    64        // staged detector window (dets)
#define WROW   68        // window dets incl 4 zero slots
#define ZSLOT  64        // zero det slot
#define GATE_U 0x43FF8000u   // bits of 511.0f

// filtered projection partials (two tap-halves), [z][b][a][det]
__device__ float g_fstore[2][B * NTH * DET];
// half4-interleaved projections [a][det][b], 256-half pads both ends
__device__ __align__(16) __half g_fh[256 + NTH * DET * 4 + 256];

// ---------------------------------------------------------------------------
// Kernel 1: ramp filter, parity-compressed, TAP-SPLIT 2 ways (blockIdx.z):
// each block sums 32 of the 64 4-tap groups; pack adds the two partials.
//   out[k] = 0.5 x[k] + sum_{d odd} g(d) x[k-d],  g(d) = -2/(pi d)^2
// ---------------------------------------------------------------------------
__global__ void __launch_bounds__(128) filter_kernel(const float* __restrict__ x)
{
    __shared__ __align__(16) float xe[256];
    __shared__ __align__(16) float xo[256];
    __shared__ __align__(16) float Tbuf[4 + 512 + 4];

    float* T = Tbuf + 4;

    const int a = blockIdx.x;
    const int b = blockIdx.y;
    const int z = blockIdx.z;          // tap half
    const int tid = threadIdx.x;

    {
        int m0 = 4 * tid;
        const float* xp = x + (b * DET + m0) * NTH + a;
        float v0 = xp[0 * NTH], v1 = xp[1 * NTH];
        float v2 = xp[2 * NTH], v3 = xp[3 * NTH];
        xe[m0 / 2]     = v0;  xo[m0 / 2]     = v1;
        xe[m0 / 2 + 1] = v2;  xo[m0 / 2 + 1] = v3;
    }
    #pragma unroll
    for (int j = tid; j < 512; j += 128) {
        int d = 2 * j - 513; if (d < 0) d = -d;
        float fd = (float)d;
        T[j] = -2.0f / (PI_F * PI_F * fd * fd);
    }
    if (tid < 4) { Tbuf[tid] = 0.0f; Tbuf[516 + tid] = 0.0f; }
    __syncthreads();

    const int odd = tid >> 6;
    const int t   = tid & 63;
    const int K0  = 4 * t;
    const int M0_beg = z * 128;
    const int M0_end = M0_beg + 128;

    float acc0 = 0.f, acc1 = 0.f, acc2 = 0.f, acc3 = 0.f;

    if (!odd) {
        int j0 = K0 + 256 - M0_beg;
        float4 tb = *reinterpret_cast<const float4*>(T + j0);
        float4 ta = *reinterpret_cast<const float4*>(T + j0 - 4);
        #pragma unroll 4
        for (int M0 = M0_beg; M0 < M0_end; M0 += 4, j0 -= 4) {
            float4 xb = *reinterpret_cast<const float4*>(xo + M0);
            float4 tn = *reinterpret_cast<const float4*>(T + j0 - 8);
            acc0 = fmaf(tb.x, xb.x, acc0); acc0 = fmaf(ta.w, xb.y, acc0);
            acc0 = fmaf(ta.z, xb.z, acc0); acc0 = fmaf(ta.y, xb.w, acc0);
            acc1 = fmaf(tb.y, xb.x, acc1); acc1 = fmaf(tb.x, xb.y, acc1);
            acc1 = fmaf(ta.w, xb.z, acc1); acc1 = fmaf(ta.z, xb.w, acc1);
            acc2 = fmaf(tb.z, xb.x, acc2); acc2 = fmaf(tb.y, xb.y, acc2);
            acc2 = fmaf(tb.x, xb.z, acc2); acc2 = fmaf(ta.w, xb.w, acc2);
            acc3 = fmaf(tb.w, xb.x, acc3); acc3 = fmaf(tb.z, xb.y, acc3);
            acc3 = fmaf(tb.y, xb.z, acc3); acc3 = fmaf(tb.x, xb.w, acc3);
            tb = ta; ta = tn;
        }
        if (z == 0) {
            float4 xc = *reinterpret_cast<const float4*>(xe + K0);
            acc0 = fmaf(0.5f, xc.x, acc0);
            acc1 = fmaf(0.5f, xc.y, acc1);
            acc2 = fmaf(0.5f, xc.z, acc2);
            acc3 = fmaf(0.5f, xc.w, acc3);
        }
    } else {
        int j0 = 256 - K0 + M0_beg;
        float4 ta = *reinterpret_cast<const float4*>(T + j0 - 4);
        float4 tb = *reinterpret_cast<const float4*>(T + j0);
        #pragma unroll 4
        for (int M0 = M0_beg; M0 < M0_end; M0 += 4, j0 += 4) {
            float4 xb = *reinterpret_cast<const float4*>(xe + M0);
            float4 tn = *reinterpret_cast<const float4*>(T + j0 + 4);
            acc0 = fmaf(tb.x, xb.x, acc0); acc0 = fmaf(tb.y, xb.y, acc0);
            acc0 = fmaf(tb.z, xb.z, acc0); acc0 = fmaf(tb.w, xb.w, acc0);
            acc1 = fmaf(ta.w, xb.x, acc1); acc1 = fmaf(tb.x, xb.y, acc1);
            acc1 = fmaf(tb.y, xb.z, acc1); acc1 = fmaf(tb.z, xb.w, acc1);
            acc2 = fmaf(ta.z, xb.x, acc2); acc2 = fmaf(ta.w, xb.y, acc2);
            acc2 = fmaf(tb.x, xb.z, acc2); acc2 = fmaf(tb.y, xb.w, acc2);
            acc3 = fmaf(ta.y, xb.x, acc3); acc3 = fmaf(ta.z, xb.y, acc3);
            acc3 = fmaf(ta.w, xb.z, acc3); acc3 = fmaf(tb.x, xb.w, acc3);
            ta = tb; tb = tn;
        }
        if (z == 0) {
            float4 xc = *reinterpret_cast<const float4*>(xo + K0);
            acc0 = fmaf(0.5f, xc.x, acc0);
            acc1 = fmaf(0.5f, xc.y, acc1);
            acc2 = fmaf(0.5f, xc.z, acc2);
            acc3 = fmaf(0.5f, xc.w, acc3);
        }
    }

    float* o = g_fstore[z] + (b * NTH + a) * DET + 8 * t + odd;
    o[0] = acc0; o[2] = acc1; o[4] = acc2; o[6] = acc3;
}

// ---------------------------------------------------------------------------
// Kernel 1b: pack (partial0 + partial1) fp32 -> half4-interleaved [a][det][b],
// AND zero the output buffer (fused; both elementwise, independent).
// ---------------------------------------------------------------------------
__global__ void __launch_bounds__(256) pack_zero_kernel(float* __restrict__ out)
{
    const int n  = NTH * DET;                 // 92160
    const int n4 = (B * OUT * OUT) / 4;       // 131044
    int idx = blockIdx.x * 256 + threadIdx.x;
    if (idx < n) {
        const float* f0 = g_fstore[0];
        const float* f1 = g_fstore[1];
        __half2 h01 = __floats2half2_rn(f0[idx]         + f1[idx],
                                        f0[idx + n]     + f1[idx + n]);
        __half2 h23 = __floats2half2_rn(f0[idx + 2 * n] + f1[idx + 2 * n],
                                        f0[idx + 3 * n] + f1[idx + 3 * n]);
        uint2 pk;
        pk.x = *reinterpret_cast<unsigned int*>(&h01);
        pk.y = *reinterpret_cast<unsigned int*>(&h23);
        *reinterpret_cast<uint2*>(g_fh + 256 + idx * 4) = pk;
    }
    if (idx < n4)
        reinterpret_cast<float4*>(out)[idx] = make_float4(0.f, 0.f, 0.f, 0.f);
}

// ---------------------------------------------------------------------------
// Kernel 2: backprojection, angle-split 6 ways (30 each), fp16 windowed PAIR
// staging (one barrier per 2 angles), uint gate, half lerp, fp32 accum,
// RED.ADD into out. launch_bounds(256,6) -> <=42 regs, one wave @ 6 CTAs/SM.
// pos = (j-RAD)*cos(th) - (i-RAD)*sin(th) + DET/2
// ---------------------------------------------------------------------------
__global__ void __launch_bounds__(256, 6) backproj_kernel(float* __restrict__ out)
{
    __shared__ __align__(16) __half win[PSTG][2][WROW * 4]; // 3264 B
    __shared__ float cs[APB];
    __shared__ float sn[APB];
    __shared__ int   w0s[APB];

    const int z  = blockIdx.z;
    const int a0 = z * APB;
    const int j0 = blockIdx.x * 32;
    const int i0 = blockIdx.y * 32;
    const int tid = threadIdx.x;
    const int tx = tid & 31;
    const int ty = tid >> 5;             // 0..7

    if (tid < APB) {
        float ang = (float)(a0 + tid) * (PI_F / 180.0f);
        float c = cosf(ang);
        float s = sinf(ang);
        cs[tid] = c;
        sn[tid] = s;
        // min over tile of pos = jf*c - xf*s + 256   (s >= 0 on [0,pi))
        float jlo = (float)(j0 - RAD), jhi = (float)(j0 + 31 - RAD);
        float xhi = (float)(i0 + 31 - RAD);
        float minpos = (c >= 0.0f ? c * jlo : c * jhi) - s * xhi + 256.0f;
        int w0 = (int)floorf(minpos) - 1;
        w0s[tid] = (w0 >> 2) << 2;       // align down to multiple of 4
    }
    // zero det slots 64..67 (uints 128..135) of all PSTG*2 windows
    if (tid < PSTG * 2 * 8) {
        int p = tid & 7;
        int w = tid >> 3;                // 0..5
        unsigned int* wu = reinterpret_cast<unsigned int*>(&win[0][0][0]);
        wu[w * (WROW * 4 / 2) + 128 + p] = 0u;
    }
    __syncthreads();   // w0s needed by staging below

    // staging: threads 0..63 copy 16B each; hw = angle-in-pair, sch = chunk
    const int hw  = (tid >> 5) & 1;
    const int sch = tid & 31;
    const __half* fb = g_fh + 256;
    unsigned int sdst[PSTG];
    #pragma unroll
    for (int st = 0; st < PSTG; st++) {
        unsigned int u;
        asm("{ .reg .u64 t; cvta.to.shared.u64 t, %1; cvt.u32.u64 %0, t; }"
            : "=r"(u) : "l"((const void*)&win[st][hw][sch * 8]));
        sdst[st] = u;
    }

    // prologue: prefetch pairs 0 and 1 into stages 0 and 1
    if (tid < 64) {
        #pragma unroll
        for (int p = 0; p < 2; p++) {
            int q = 2 * p + hw;
            const __half* src = fb + ((a0 + q) * DET + w0s[q]) * 4 + sch * 8;
            asm volatile("cp.async.ca.shared.global [%0], [%1], 16;\n"
                         :: "r"(sdst[p]), "l"(src) : "memory");
        }
    }
    asm volatile("cp.async.commit_group;\n" ::: "memory");
    asm volatile("cp.async.commit_group;\n" ::: "memory");

    const float jf = (float)(j0 + tx - RAD);
    float xpr[4];
    #pragma unroll
    for (int r = 0; r < 4; r++) xpr[r] = (float)(i0 + ty + 8 * r - RAD);

    float acc[B][4];
    #pragma unroll
    for (int bb = 0; bb < B; bb++)
        #pragma unroll
        for (int r = 0; r < 4; r++) acc[bb][r] = 0.0f;

    const int npairs = APB / 2;          // 15
    int st = 0;
    for (int p = 0; p < npairs; p++) {
        if (p < npairs - 1) {
            asm volatile("cp.async.wait_group 1;\n" ::: "memory");
        } else {
            asm volatile("cp.async.wait_group 0;\n" ::: "memory");
        }
        __syncthreads();   // pair p staged & visible; stage (st+2)%3 free

        {
            int nst = st + 2; if (nst >= PSTG) nst -= PSTG;
            if (p + 2 < npairs && tid < 64) {
                int q = 2 * (p + 2) + hw;
                const __half* src = fb + ((a0 + q) * DET + w0s[q]) * 4
                                  + sch * 8;
                asm volatile("cp.async.ca.shared.global [%0], [%1], 16;\n"
                             :: "r"(sdst[nst]), "l"(src) : "memory");
            }
            asm volatile("cp.async.commit_group;\n" ::: "memory");
        }

        #pragma unroll
        for (int h = 0; h < 2; h++) {
            const int q = 2 * p + h;
            const float c = cs[q];
            const float s = sn[q];
            const int   w0a = w0s[q];
            const float base = fmaf(jf, c, (float)(DET / 2));
            const __half* wp = win[st][h];

            #pragma unroll
            for (int r = 0; r < 4; r++) {
                float pos = fmaf(-xpr[r], s, base);
                int   idx = __float2int_rd(pos);
                float w   = pos - (float)idx;
                // gate: pos in [0,511] <=> float bits <= bits(511.0f)
                int sel = (__float_as_uint(pos) <= GATE_U) ? (idx - w0a)
                                                           : ZSLOT;
                uint2 qa = *reinterpret_cast<const uint2*>(wp + sel * 4);
                uint2 qb = *reinterpret_cast<const uint2*>(wp + sel * 4 + 4);
                __half2 w2 = __float2half2_rn(w);
                __half2 qa01 = *reinterpret_cast<__half2*>(&qa.x);
                __half2 qa23 = *reinterpret_cast<__half2*>(&qa.y);
                __half2 qb01 = *reinterpret_cast<__half2*>(&qb.x);
                __half2 qb23 = *reinterpret_cast<__half2*>(&qb.y);
                __half2 v01 = __hfma2(w2, __hsub2(qb01, qa01), qa01);
                __half2 v23 = __hfma2(w2, __hsub2(qb23, qa23), qa23);
                float2 f01 = __half22float2(v01);
                float2 f23 = __half22float2(v23);
                acc[0][r] += f01.x;
                acc[1][r] += f01.y;
                acc[2][r] += f23.x;
                acc[3][r] += f23.y;
            }
        }

        st++; if (st >= PSTG) st -= PSTG;
    }

    const float scale = PI_F / (2.0f * (float)NTH);
    const int j = j0 + tx;
    if (j < OUT) {
        #pragma unroll
        for (int bb = 0; bb < B; bb++) {
            #pragma unroll
            for (int r = 0; r < 4; r++) {
                int i = i0 + ty + 8 * r;
                if (i < OUT)
                    atomicAdd(&out[(bb * OUT + i) * OUT + j], acc[bb][r] * scale);
            }
        }
    }
}

extern "C" void kernel_launch(void* const* d_in, const int* in_sizes, int n_in,
                              void* d_out, int out_size)
{
    const float* x = (const float*)d_in[0];
    float* out = (float*)d_out;

    filter_kernel<<<dim3(NTH, B, 2), 128>>>(x);

    int n4 = (B * OUT * OUT) / 4;
    pack_zero_kernel<<<(n4 + 255) / 256, 256>>>(out);

    dim3 grid((OUT + 31) / 32, (OUT + 31) / 32, NSPLIT);   // 12 x 12 x 6
    backproj_kernel<<<grid, 256>>>(out);
}